// round 8
// baseline (speedup 1.0000x reference)
#include <cuda_runtime.h>
#include <cuda_bf16.h>
#include <cstdint>

typedef __nv_bfloat16 bf;

// ---------------- problem constants ----------------
#define BB   2
#define SS   4096
#define DD   2048
#define HH   16
#define HD   128
#define CHUNK 64
#define NC   64
#define MROWS 8192
#define NBH  32
#define QSCALE 0.08838834764831845f
#define WSZ  (DD * DD)

// ---------------- scratch (device globals) ----------------
__device__ __align__(256) bf g_xhi[(size_t)MROWS * DD];
__device__ __align__(256) bf g_xlo[(size_t)MROWS * DD];
__device__ __align__(256) bf g_whi[(size_t)4 * WSZ];
__device__ __align__(256) bf g_wlo[(size_t)4 * WSZ];
__device__ __align__(256) bf g_qhi[(size_t)MROWS * DD];
__device__ __align__(256) bf g_qlo[(size_t)MROWS * DD];
__device__ __align__(256) bf g_khi[(size_t)MROWS * DD];
__device__ __align__(256) bf g_klo[(size_t)MROWS * DD];
__device__ __align__(256) bf g_vhi[(size_t)MROWS * DD];
__device__ __align__(256) bf g_vlo[(size_t)MROWS * DD];
__device__ __align__(256) bf g_ohi[(size_t)MROWS * DD];
__device__ __align__(256) bf g_olo[(size_t)MROWS * DD];
__device__ float g_KV[(size_t)NBH * NC * HD * HD];
__device__ __align__(256) bf g_Shi[(size_t)NBH * NC * HD * HD];
__device__ __align__(256) bf g_Slo[(size_t)NBH * NC * HD * HD];

// ---------------- helpers ----------------
__device__ __forceinline__ uint32_t smem_u32(const void* p) {
    return (uint32_t)__cvta_generic_to_shared(p);
}
__device__ __forceinline__ void cp16(uint32_t d, const void* s) {
    asm volatile("cp.async.cg.shared.global [%0], [%1], 16;\n" :: "r"(d), "l"(s));
}
__device__ __forceinline__ void ldsm4(uint32_t* r, uint32_t a) {
    asm volatile("ldmatrix.sync.aligned.m8n8.x4.shared.b16 {%0,%1,%2,%3}, [%4];\n"
                 : "=r"(r[0]), "=r"(r[1]), "=r"(r[2]), "=r"(r[3]) : "r"(a));
}
__device__ __forceinline__ void ldsm4t(uint32_t* r, uint32_t a) {
    asm volatile("ldmatrix.sync.aligned.m8n8.x4.trans.shared.b16 {%0,%1,%2,%3}, [%4];\n"
                 : "=r"(r[0]), "=r"(r[1]), "=r"(r[2]), "=r"(r[3]) : "r"(a));
}
__device__ __forceinline__ void mma_bf16(float* c, const uint32_t* a, const uint32_t* b) {
    asm volatile("mma.sync.aligned.m16n8k16.row.col.f32.bf16.bf16.f32 "
                 "{%0,%1,%2,%3}, {%4,%5,%6,%7}, {%8,%9}, {%0,%1,%2,%3};\n"
                 : "+f"(c[0]), "+f"(c[1]), "+f"(c[2]), "+f"(c[3])
                 : "r"(a[0]), "r"(a[1]), "r"(a[2]), "r"(a[3]), "r"(b[0]), "r"(b[1]));
}
__device__ __forceinline__ uint32_t pk2(float a, float b) {
    __nv_bfloat162 t = __floats2bfloat162_rn(a, b);
    return *(uint32_t*)&t;
}
__device__ __forceinline__ void split2(float a, float b, uint32_t& H, uint32_t& L) {
    float ha = __bfloat162float(__float2bfloat16(a));
    float hb = __bfloat162float(__float2bfloat16(b));
    H = pk2(a, b);
    L = pk2(a - ha, b - hb);
}

// ---------------- fp32 -> bf16 hi/lo split ----------------
__global__ __launch_bounds__(256) void cvt_kernel(const float* __restrict__ src,
                                                  bf* __restrict__ hi, bf* __restrict__ lo) {
    size_t i = (size_t)blockIdx.x * 256 + threadIdx.x;
    float4 v = ((const float4*)src)[i];
    float h0 = __bfloat162float(__float2bfloat16(v.x));
    float h1 = __bfloat162float(__float2bfloat16(v.y));
    float h2 = __bfloat162float(__float2bfloat16(v.z));
    float h3 = __bfloat162float(__float2bfloat16(v.w));
    uint2 H, L;
    H.x = pk2(v.x, v.y);           H.y = pk2(v.z, v.w);
    L.x = pk2(v.x - h0, v.y - h1); L.y = pk2(v.z - h2, v.w - h3);
    ((uint2*)hi)[i] = H;
    ((uint2*)lo)[i] = L;
}

// ================= bf16 hi/lo GEMM: C = alpha*(A)(B^T), CTA 128x256 =================
// 4-stage cp.async pipeline, K-step 32, single __syncthreads per iteration.
#define KIT2 64                 // K iterations of 32
#define STG_B 49152             // A 16KB + B 32KB
#define GEMM_SMEM (4 * STG_B)   // 196608
// stage row format: 128B = 8 chunks of 16B; chunks 0-3 = hi k0..31, 4-7 = lo.
// A rows 0..127 at stage+0, B rows 0..255 at stage+16384.

__device__ __forceinline__ void issue_stage(uint32_t sbase,
        const bf* __restrict__ Ahi, const bf* __restrict__ Alo,
        const bf* __restrict__ Bhi, const bf* __restrict__ Blo,
        int k0, int tid) {
    #pragma unroll
    for (int i = 0; i < 4; i++) {             // A: 128 rows x 8 chunks
        int idx = tid + i * 256;
        int row = idx >> 3, c = idx & 7;
        const bf* src = (c < 4 ? Ahi : Alo) + (size_t)row * DD + k0 + (c & 3) * 8;
        cp16(sbase + row * 128 + (((uint32_t)c ^ (row & 7)) << 4), src);
    }
    #pragma unroll
    for (int i = 0; i < 8; i++) {             // B: 256 rows x 8 chunks
        int idx = tid + i * 256;
        int row = idx >> 3, c = idx & 7;
        const bf* src = (c < 4 ? Bhi : Blo) + (size_t)row * DD + k0 + (c & 3) * 8;
        cp16(sbase + 16384 + row * 128 + (((uint32_t)c ^ (row & 7)) << 4), src);
    }
    asm volatile("cp.async.commit_group;\n" ::: "memory");
}

__device__ __forceinline__ void stage_compute(uint32_t sbase, int lane,
                                              int wm0, int wn0, float acc[4][8][4]) {
    const int arow = (lane & 7) + ((lane >> 3) & 1) * 8;
    const int asel = lane >> 4;
    const int brow = (lane & 7) + ((lane >> 4) << 3);
    const int bsel = (lane >> 3) & 1;
    #pragma unroll
    for (int ks = 0; ks < 2; ks++) {
        uint32_t ahi[4][4], alo[4][4];
        #pragma unroll
        for (int mf = 0; mf < 4; mf++) {
            int row = wm0 + mf * 16 + arow;
            int c = ks * 2 + asel;
            ldsm4(ahi[mf], sbase + row * 128 + (((uint32_t)c ^ (row & 7)) << 4));
            ldsm4(alo[mf], sbase + row * 128 + (((uint32_t)(c + 4) ^ (row & 7)) << 4));
        }
        uint32_t bhi[4][4], blo[4][4];
        #pragma unroll
        for (int nq = 0; nq < 4; nq++) {
            int row = wn0 + nq * 16 + brow;
            int c = ks * 2 + bsel;
            ldsm4(bhi[nq], sbase + 16384 + row * 128 + (((uint32_t)c ^ (row & 7)) << 4));
            ldsm4(blo[nq], sbase + 16384 + row * 128 + (((uint32_t)(c + 4) ^ (row & 7)) << 4));
        }
        #pragma unroll
        for (int mf = 0; mf < 4; mf++)
            #pragma unroll
            for (int nf = 0; nf < 8; nf++) {
                const uint32_t* bh = &bhi[nf >> 1][(nf & 1) * 2];
                const uint32_t* bl = &blo[nf >> 1][(nf & 1) * 2];
                mma_bf16(acc[mf][nf], ahi[mf], bh);
                mma_bf16(acc[mf][nf], ahi[mf], bl);
                mma_bf16(acc[mf][nf], alo[mf], bh);
            }
    }
}

// Fused multi-projection GEMM. If Cf != null: single fp32 output (grid.x = 8).
// Else grid.x = 24; projection p = blockIdx.x >> 3 routes to (C0,C1,C2) hi/lo,
// with alpha = QSCALE on projection 0.
__global__ __launch_bounds__(256, 1) void gemm_mma(
        const bf* __restrict__ Ahi, const bf* __restrict__ Alo,
        const bf* __restrict__ Bhi, const bf* __restrict__ Blo,
        float* __restrict__ Cf,
        uint32_t* __restrict__ C0h, uint32_t* __restrict__ C0l,
        uint32_t* __restrict__ C1h, uint32_t* __restrict__ C1l,
        uint32_t* __restrict__ C2h, uint32_t* __restrict__ C2l) {
    extern __shared__ char smc[];
    const uint32_t sb = smem_u32(smc);
    const int tid = threadIdx.x, lane = tid & 31, w = tid >> 5;
    const int bm0 = blockIdx.y * 128;
    const int bnG = blockIdx.x * 256;          // global n across projections
    const int wm0 = (w >> 2) * 64, wn0 = (w & 3) * 64;
    const bf* At_hi = Ahi + (size_t)bm0 * DD;
    const bf* At_lo = Alo + (size_t)bm0 * DD;
    const bf* Bt_hi = Bhi + (size_t)bnG * DD;
    const bf* Bt_lo = Blo + (size_t)bnG * DD;

    float acc[4][8][4];
    #pragma unroll
    for (int a = 0; a < 4; a++)
        #pragma unroll
        for (int b = 0; b < 8; b++)
            #pragma unroll
            for (int c = 0; c < 4; c++) acc[a][b][c] = 0.f;

    issue_stage(sb + 0 * STG_B, At_hi, At_lo, Bt_hi, Bt_lo, 0,  tid);
    issue_stage(sb + 1 * STG_B, At_hi, At_lo, Bt_hi, Bt_lo, 32, tid);
    issue_stage(sb + 2 * STG_B, At_hi, At_lo, Bt_hi, Bt_lo, 64, tid);

    for (int it = 0; it < KIT2; ++it) {
        if (it < KIT2 - 2)      asm volatile("cp.async.wait_group 2;\n" ::: "memory");
        else if (it == KIT2 - 2) asm volatile("cp.async.wait_group 1;\n" ::: "memory");
        else                     asm volatile("cp.async.wait_group 0;\n" ::: "memory");
        __syncthreads();
        if (it + 3 < KIT2)
            issue_stage(sb + ((it + 3) & 3) * STG_B, At_hi, At_lo, Bt_hi, Bt_lo,
                        (it + 3) * 32, tid);
        stage_compute(sb + (it & 3) * STG_B, lane, wm0, wn0, acc);
    }

    const int proj = bnG >> 11;                // 0..2 (fused path)
    const int ncol0 = bnG & 2047;
    const float alpha = (Cf == nullptr && proj == 0) ? QSCALE : 1.f;
    uint32_t* Chi = (proj == 0) ? C0h : (proj == 1) ? C1h : C2h;
    uint32_t* Clo = (proj == 0) ? C0l : (proj == 1) ? C1l : C2l;

    const int r0 = lane >> 2, c0 = lane & 3;
    #pragma unroll
    for (int mf = 0; mf < 4; mf++)
        #pragma unroll
        for (int nf = 0; nf < 8; nf++) {
            int row = bm0 + wm0 + mf * 16 + r0;
            int col = ncol0 + wn0 + nf * 8 + c0 * 2;
            float v0 = alpha * acc[mf][nf][0], v1 = alpha * acc[mf][nf][1];
            float v2 = alpha * acc[mf][nf][2], v3 = alpha * acc[mf][nf][3];
            if (Cf) {
                *(float2*)(Cf + (size_t)row * DD + col) = make_float2(v0, v1);
                *(float2*)(Cf + (size_t)(row + 8) * DD + col) = make_float2(v2, v3);
            } else {
                size_t pA = (size_t)row * (DD / 2) + (col >> 1);
                size_t pB = (size_t)(row + 8) * (DD / 2) + (col >> 1);
                uint32_t H, L;
                split2(v0, v1, H, L); Chi[pA] = H; Clo[pA] = L;
                split2(v2, v3, H, L); Chi[pB] = H; Clo[pB] = L;
            }
        }
}

// ================= kv: KV[d][e] = sum_s K[s][d] V[s][e]  (tensor) =================
#define KV_SMEM 65536
__global__ __launch_bounds__(256) void kv_mma(
        const bf* __restrict__ Khi, const bf* __restrict__ Klo,
        const bf* __restrict__ Vhi, const bf* __restrict__ Vlo,
        float* __restrict__ KV) {
    extern __shared__ char smc[];
    const uint32_t sb = smem_u32(smc);
    const int tid = threadIdx.x, lane = tid & 31, w = tid >> 5;
    const int blk = blockIdx.x;
    const int bh = blk / NC, cch = blk % NC;
    const int b = bh / HH, h = bh % HH;
    const size_t grow = (size_t)(b * SS + cch * CHUNK);

    const bf* tiles[4] = {Khi, Klo, Vhi, Vlo};
    #pragma unroll
    for (int i = 0; i < 16; i++) {
        const int t4 = i >> 2;
        int idx = tid + (i & 3) * 256;
        int row = idx >> 4, c = idx & 15;
        const bf* src = tiles[t4] + (grow + row) * DD + h * HD + c * 8;
        cp16(sb + t4 * 16384 + row * 256 + (((uint32_t)c ^ (row & 7)) << 4), src);
    }
    asm volatile("cp.async.commit_group;\ncp.async.wait_group 0;\n" ::: "memory");
    __syncthreads();

    const int md0 = (w >> 1) * 32, ne0 = (w & 1) * 64;
    const int j = lane & 7, g1 = (lane >> 3) & 1, g2 = lane >> 4;

    float acc[2][8][4];
    #pragma unroll
    for (int a = 0; a < 2; a++)
        #pragma unroll
        for (int n = 0; n < 8; n++)
            #pragma unroll
            for (int e = 0; e < 4; e++) acc[a][n][e] = 0.f;

    #pragma unroll
    for (int kb = 0; kb < 4; kb++) {
        uint32_t ah[2][4], al[2][4];
        #pragma unroll
        for (int mf = 0; mf < 2; mf++) {
            int row = kb * 16 + g2 * 8 + j;
            int c = (md0 >> 3) + mf * 2 + g1;
            ldsm4t(ah[mf], sb + 0     + row * 256 + (((uint32_t)c ^ (row & 7)) << 4));
            ldsm4t(al[mf], sb + 16384 + row * 256 + (((uint32_t)c ^ (row & 7)) << 4));
        }
        uint32_t vh[4][4], vl[4][4];
        #pragma unroll
        for (int nf2 = 0; nf2 < 4; nf2++) {
            int row = kb * 16 + g1 * 8 + j;
            int c = (ne0 >> 3) + nf2 * 2 + g2;
            ldsm4t(vh[nf2], sb + 32768 + row * 256 + (((uint32_t)c ^ (row & 7)) << 4));
            ldsm4t(vl[nf2], sb + 49152 + row * 256 + (((uint32_t)c ^ (row & 7)) << 4));
        }
        #pragma unroll
        for (int mf = 0; mf < 2; mf++)
            #pragma unroll
            for (int nf = 0; nf < 8; nf++) {
                const uint32_t* bh2 = &vh[nf >> 1][(nf & 1) * 2];
                const uint32_t* bl2 = &vl[nf >> 1][(nf & 1) * 2];
                mma_bf16(acc[mf][nf], ah[mf], bh2);
                mma_bf16(acc[mf][nf], ah[mf], bl2);
                mma_bf16(acc[mf][nf], al[mf], bh2);
            }
    }
    float* out = KV + (size_t)blk * (HD * HD);
    const int r0 = lane >> 2, c0 = (lane & 3) * 2;
    #pragma unroll
    for (int mf = 0; mf < 2; mf++)
        #pragma unroll
        for (int nf = 0; nf < 8; nf++) {
            int d = md0 + mf * 16 + r0;
            int e = ne0 + nf * 8 + c0;
            *(float2*)(out + (size_t)d * HD + e) = make_float2(acc[mf][nf][0], acc[mf][nf][1]);
            *(float2*)(out + (size_t)(d + 8) * HD + e) = make_float2(acc[mf][nf][2], acc[mf][nf][3]);
        }
}

// ================= exclusive chunk scan: fp32 KV -> bf16 hi/lo S =================
__global__ __launch_bounds__(256) void scan_kernel(const float* __restrict__ KV,
                                                   bf* __restrict__ Shi, bf* __restrict__ Slo) {
    size_t g = (size_t)blockIdx.x * 256 + threadIdx.x;
    int bh = (int)(g >> 13);
    int p  = (int)(g & 8191);
    const float2* src = (const float2*)(KV + (size_t)bh * NC * HD * HD) + p;
    uint32_t* dh = (uint32_t*)(Shi + (size_t)bh * NC * HD * HD) + p;
    uint32_t* dl = (uint32_t*)(Slo + (size_t)bh * NC * HD * HD) + p;
    float a0 = 0.f, a1 = 0.f;
    for (int c = 0; c < NC; c++) {
        float2 t = src[(size_t)c * 8192];
        float h0 = __bfloat162float(__float2bfloat16(a0));
        float h1 = __bfloat162float(__float2bfloat16(a1));
        dh[(size_t)c * 8192] = pk2(a0, a1);
        dl[(size_t)c * 8192] = pk2(a0 - h0, a1 - h1);
        a0 += t.x; a1 += t.y;
    }
}

// ================= attn: o = tril(q k^T) v + q S  (tensor) =================
#define ATTN_SMEM 163840
#define AQHI 0
#define AQLO 16384
#define AKHI 32768
#define AKLO 49152
#define AVHI 65536
#define AVLO 81920
#define ASHI 98304
#define ASLO 131072

__global__ __launch_bounds__(256) void attn_mma(
        const bf* __restrict__ Qhi, const bf* __restrict__ Qlo,
        const bf* __restrict__ Khi, const bf* __restrict__ Klo,
        const bf* __restrict__ Vhi, const bf* __restrict__ Vlo,
        const bf* __restrict__ Shi, const bf* __restrict__ Slo,
        uint32_t* __restrict__ Ohi, uint32_t* __restrict__ Olo) {
    extern __shared__ char smc[];
    const uint32_t sb = smem_u32(smc);
    const int tid = threadIdx.x, lane = tid & 31, w = tid >> 5;
    const int blk = blockIdx.x;
    const int bh = blk / NC, cch = blk % NC;
    const int b = bh / HH, h = bh % HH;
    const size_t grow = (size_t)(b * SS + cch * CHUNK);

    const bf* tiles[6] = {Qhi, Qlo, Khi, Klo, Vhi, Vlo};
    #pragma unroll
    for (int i = 0; i < 24; i++) {
        const int t6 = i >> 2;
        int idx = tid + (i & 3) * 256;
        int row = idx >> 4, c = idx & 15;
        const bf* src = tiles[t6] + (grow + row) * DD + h * HD + c * 8;
        cp16(sb + t6 * 16384 + row * 256 + (((uint32_t)c ^ (row & 7)) << 4), src);
    }
    const size_t sgb = (size_t)blk * (HD * HD);
    #pragma unroll
    for (int i = 0; i < 16; i++) {
        const int pl = i >> 3;
        int idx = tid + (i & 7) * 256;
        int row = idx >> 4, c = idx & 15;
        const bf* src = (pl ? Slo : Shi) + sgb + (size_t)row * HD + c * 8;
        cp16(sb + ASHI + pl * 32768 + row * 256 + (((uint32_t)c ^ (row & 7)) << 4), src);
    }
    asm volatile("cp.async.commit_group;\ncp.async.wait_group 0;\n" ::: "memory");
    __syncthreads();

    const int mrow = (w >> 1) * 16, nh = w & 1;
    const int arow = (lane & 7) + ((lane >> 3) & 1) * 8;
    const int asel = lane >> 4;
    const int brow = (lane & 7) + ((lane >> 4) << 3);
    const int bsel = (lane >> 3) & 1;
    const int j = lane & 7, g1 = (lane >> 3) & 1, g2 = lane >> 4;

    float qk[8][4];
    #pragma unroll
    for (int n = 0; n < 8; n++)
        #pragma unroll
        for (int e = 0; e < 4; e++) qk[n][e] = 0.f;

    #pragma unroll
    for (int kb = 0; kb < 8; kb++) {
        uint32_t qh[4], ql[4];
        {
            int row = mrow + arow;
            int c = kb * 2 + asel;
            ldsm4(qh, sb + AQHI + row * 256 + (((uint32_t)c ^ (row & 7)) << 4));
            ldsm4(ql, sb + AQLO + row * 256 + (((uint32_t)c ^ (row & 7)) << 4));
        }
        uint32_t kh[4][4], kl[4][4];
        #pragma unroll
        for (int nq = 0; nq < 4; nq++) {
            int row = nq * 16 + brow;
            int c = kb * 2 + bsel;
            ldsm4(kh[nq], sb + AKHI + row * 256 + (((uint32_t)c ^ (row & 7)) << 4));
            ldsm4(kl[nq], sb + AKLO + row * 256 + (((uint32_t)c ^ (row & 7)) << 4));
        }
        #pragma unroll
        for (int nf = 0; nf < 8; nf++) {
            const uint32_t* bh2 = &kh[nf >> 1][(nf & 1) * 2];
            const uint32_t* bl2 = &kl[nf >> 1][(nf & 1) * 2];
            mma_bf16(qk[nf], qh, bh2);
            mma_bf16(qk[nf], qh, bl2);
            mma_bf16(qk[nf], ql, bh2);
        }
    }
    const int r0 = lane >> 2, c0 = (lane & 3) * 2;
    #pragma unroll
    for (int nf = 0; nf < 8; nf++)
        #pragma unroll
        for (int e = 0; e < 4; e++) {
            int rloc = mrow + r0 + ((e >= 2) ? 8 : 0);
            int scol = nf * 8 + c0 + (e & 1);
            if (scol > rloc) qk[nf][e] = 0.f;
        }

    float o[8][4];
    #pragma unroll
    for (int n = 0; n < 8; n++)
        #pragma unroll
        for (int e = 0; e < 4; e++) o[n][e] = 0.f;

    #pragma unroll
    for (int kb2 = 0; kb2 < 4; kb2++) {
        uint32_t Ah[4], Al[4];
        split2(qk[2 * kb2][0],     qk[2 * kb2][1],     Ah[0], Al[0]);
        split2(qk[2 * kb2][2],     qk[2 * kb2][3],     Ah[1], Al[1]);
        split2(qk[2 * kb2 + 1][0], qk[2 * kb2 + 1][1], Ah[2], Al[2]);
        split2(qk[2 * kb2 + 1][2], qk[2 * kb2 + 1][3], Ah[3], Al[3]);
        uint32_t vh[4][4], vl[4][4];
        #pragma unroll
        for (int nf2 = 0; nf2 < 4; nf2++) {
            int row = kb2 * 16 + g1 * 8 + j;
            int c = nh * 8 + nf2 * 2 + g2;
            ldsm4t(vh[nf2], sb + AVHI + row * 256 + (((uint32_t)c ^ (row & 7)) << 4));
            ldsm4t(vl[nf2], sb + AVLO + row * 256 + (((uint32_t)c ^ (row & 7)) << 4));
        }
        #pragma unroll
        for (int nf = 0; nf < 8; nf++) {
            const uint32_t* bh2 = &vh[nf >> 1][(nf & 1) * 2];
            const uint32_t* bl2 = &vl[nf >> 1][(nf & 1) * 2];
            mma_bf16(o[nf], Ah, bh2);
            mma_bf16(o[nf], Ah, bl2);
            mma_bf16(o[nf], Al, bh2);
        }
    }
    #pragma unroll
    for (int kb = 0; kb < 8; kb++) {
        uint32_t qh[4], ql[4];
        {
            int row = mrow + arow;
            int c = kb * 2 + asel;
            ldsm4(qh, sb + AQHI + row * 256 + (((uint32_t)c ^ (row & 7)) << 4));
            ldsm4(ql, sb + AQLO + row * 256 + (((uint32_t)c ^ (row & 7)) << 4));
        }
        uint32_t sh[4][4], sl[4][4];
        #pragma unroll
        for (int nf2 = 0; nf2 < 4; nf2++) {
            int row = kb * 16 + g1 * 8 + j;
            int c = nh * 8 + nf2 * 2 + g2;
            ldsm4t(sh[nf2], sb + ASHI + row * 256 + (((uint32_t)c ^ (row & 7)) << 4));
            ldsm4t(sl[nf2], sb + ASLO + row * 256 + (((uint32_t)c ^ (row & 7)) << 4));
        }
        #pragma unroll
        for (int nf = 0; nf < 8; nf++) {
            const uint32_t* bh2 = &sh[nf >> 1][(nf & 1) * 2];
            const uint32_t* bl2 = &sl[nf >> 1][(nf & 1) * 2];
            mma_bf16(o[nf], qh, bh2);
            mma_bf16(o[nf], qh, bl2);
            mma_bf16(o[nf], ql, bh2);
        }
    }
    #pragma unroll
    for (int nf = 0; nf < 8; nf++) {
        int col = h * HD + nh * 64 + nf * 8 + c0;
        size_t pA = (grow + mrow + r0) * (DD / 2) + (col >> 1);
        size_t pB = (grow + mrow + r0 + 8) * (DD / 2) + (col >> 1);
        uint32_t H, L;
        split2(o[nf][0], o[nf][1], H, L); Ohi[pA] = H; Olo[pA] = L;
        split2(o[nf][2], o[nf][3], H, L); Ohi[pB] = H; Olo[pB] = L;
    }
}

// ---------------------------------------------------------------------------
extern "C" void kernel_launch(void* const* d_in, const int* in_sizes, int n_in,
                              void* d_out, int out_size) {
    const float* x  = (const float*)d_in[0];
    const float* Wq = (const float*)d_in[1];
    const float* Wk = (const float*)d_in[2];
    const float* Wv = (const float*)d_in[3];
    const float* Wo = (const float*)d_in[4];
    float* out = (float*)d_out;

    bf *pxhi, *pxlo, *pwhi, *pwlo, *pqhi, *pqlo, *pkhi, *pklo, *pvhi, *pvlo;
    bf *pohi, *polo, *pShi, *pSlo;
    float* pKV;
    cudaGetSymbolAddress((void**)&pxhi, g_xhi);
    cudaGetSymbolAddress((void**)&pxlo, g_xlo);
    cudaGetSymbolAddress((void**)&pwhi, g_whi);
    cudaGetSymbolAddress((void**)&pwlo, g_wlo);
    cudaGetSymbolAddress((void**)&pqhi, g_qhi);
    cudaGetSymbolAddress((void**)&pqlo, g_qlo);
    cudaGetSymbolAddress((void**)&pkhi, g_khi);
    cudaGetSymbolAddress((void**)&pklo, g_klo);
    cudaGetSymbolAddress((void**)&pvhi, g_vhi);
    cudaGetSymbolAddress((void**)&pvlo, g_vlo);
    cudaGetSymbolAddress((void**)&pohi, g_ohi);
    cudaGetSymbolAddress((void**)&polo, g_olo);
    cudaGetSymbolAddress((void**)&pShi, g_Shi);
    cudaGetSymbolAddress((void**)&pSlo, g_Slo);
    cudaGetSymbolAddress((void**)&pKV,  g_KV);

    cudaFuncSetAttribute(gemm_mma, cudaFuncAttributeMaxDynamicSharedMemorySize, GEMM_SMEM);
    cudaFuncSetAttribute(kv_mma,   cudaFuncAttributeMaxDynamicSharedMemorySize, KV_SMEM);
    cudaFuncSetAttribute(attn_mma, cudaFuncAttributeMaxDynamicSharedMemorySize, ATTN_SMEM);

    // split inputs
    cvt_kernel<<<(MROWS * DD) / 1024, 256>>>(x, pxhi, pxlo);
    cvt_kernel<<<WSZ / 1024, 256>>>(Wq, pwhi + 0 * (size_t)WSZ, pwlo + 0 * (size_t)WSZ);
    cvt_kernel<<<WSZ / 1024, 256>>>(Wk, pwhi + 1 * (size_t)WSZ, pwlo + 1 * (size_t)WSZ);
    cvt_kernel<<<WSZ / 1024, 256>>>(Wv, pwhi + 2 * (size_t)WSZ, pwlo + 2 * (size_t)WSZ);
    cvt_kernel<<<WSZ / 1024, 256>>>(Wo, pwhi + 3 * (size_t)WSZ, pwlo + 3 * (size_t)WSZ);

    // fused Q,K,V projections: B = [Wq; Wk; Wv] contiguous in g_whi
    dim3 qkvgrid(3 * DD / 256, MROWS / 128);   // (24, 64)
    gemm_mma<<<qkvgrid, 256, GEMM_SMEM>>>(pxhi, pxlo, pwhi, pwlo, nullptr,
                                          (uint32_t*)pqhi, (uint32_t*)pqlo,
                                          (uint32_t*)pkhi, (uint32_t*)pklo,
                                          (uint32_t*)pvhi, (uint32_t*)pvlo);

    kv_mma<<<NBH * NC, 256, KV_SMEM>>>(pkhi, pklo, pvhi, pvlo, pKV);
    scan_kernel<<<(NBH * 8192) / 256, 256>>>(pKV, pShi, pSlo);
    attn_mma<<<NBH * NC, 256, ATTN_SMEM>>>(pqhi, pqlo, pkhi, pklo, pvhi, pvlo,
                                           pShi, pSlo, (uint32_t*)pohi, (uint32_t*)polo);

    // output projection
    dim3 ogrid(DD / 256, MROWS / 128);         // (8, 64)
    gemm_mma<<<ogrid, 256, GEMM_SMEM>>>(pohi, polo, pwhi + 3 * (size_t)WSZ, pwlo + 3 * (size_t)WSZ,
                                        out, nullptr, nullptr, nullptr, nullptr, nullptr, nullptr);

    (void)in_sizes; (void)n_in; (void)out_size;
}

// round 9
// speedup vs baseline: 1.0559x; 1.0559x over previous
#include <cuda_runtime.h>
#include <cuda_fp16.h>
#include <cstdint>

// ---------------- problem constants ----------------
#define BB   2
#define SS   4096
#define DD   2048
#define HH   16
#define HD   128
#define CHUNK 64
#define NC   64
#define MROWS 8192
#define NBH  32
#define QSCALE 0.08838834764831845f
#define WSZ  (DD * DD)

// ---------------- scratch (device globals) ----------------
__device__ __align__(256) __half g_x1[(size_t)MROWS * DD];
__device__ __align__(256) __half g_x2[(size_t)MROWS * DD];
__device__ __align__(256) __half g_w1[(size_t)4 * WSZ];
__device__ __align__(256) __half g_q1[(size_t)MROWS * DD];
__device__ __align__(256) __half g_q2[(size_t)MROWS * DD];
__device__ __align__(256) __half g_k1[(size_t)MROWS * DD];
__device__ __align__(256) __half g_k2[(size_t)MROWS * DD];
__device__ __align__(256) __half g_v1[(size_t)MROWS * DD];
__device__ __align__(256) __half g_o1[(size_t)MROWS * DD];
__device__ __align__(256) __half g_o2[(size_t)MROWS * DD];
__device__ float g_KV[(size_t)NBH * NC * HD * HD];
__device__ __align__(256) __half g_S1[(size_t)NBH * NC * HD * HD];

// ---------------- helpers ----------------
__device__ __forceinline__ uint32_t smem_u32(const void* p) {
    return (uint32_t)__cvta_generic_to_shared(p);
}
__device__ __forceinline__ void cp16(uint32_t d, const void* s) {
    asm volatile("cp.async.cg.shared.global [%0], [%1], 16;\n" :: "r"(d), "l"(s));
}
__device__ __forceinline__ void ldsm4(uint32_t* r, uint32_t a) {
    asm volatile("ldmatrix.sync.aligned.m8n8.x4.shared.b16 {%0,%1,%2,%3}, [%4];\n"
                 : "=r"(r[0]), "=r"(r[1]), "=r"(r[2]), "=r"(r[3]) : "r"(a));
}
__device__ __forceinline__ void ldsm4t(uint32_t* r, uint32_t a) {
    asm volatile("ldmatrix.sync.aligned.m8n8.x4.trans.shared.b16 {%0,%1,%2,%3}, [%4];\n"
                 : "=r"(r[0]), "=r"(r[1]), "=r"(r[2]), "=r"(r[3]) : "r"(a));
}
__device__ __forceinline__ void mma_f16(float* c, const uint32_t* a, const uint32_t* b) {
    asm volatile("mma.sync.aligned.m16n8k16.row.col.f32.f16.f16.f32 "
                 "{%0,%1,%2,%3}, {%4,%5,%6,%7}, {%8,%9}, {%0,%1,%2,%3};\n"
                 : "+f"(c[0]), "+f"(c[1]), "+f"(c[2]), "+f"(c[3])
                 : "r"(a[0]), "r"(a[1]), "r"(a[2]), "r"(a[3]), "r"(b[0]), "r"(b[1]));
}
__device__ __forceinline__ uint32_t pk2h(float a, float b) {
    __half2 t = __floats2half2_rn(a, b);
    return *(uint32_t*)&t;
}
__device__ __forceinline__ void split2h(float a, float b, uint32_t& H, uint32_t& L) {
    float ha = __half2float(__float2half_rn(a));
    float hb = __half2float(__float2half_rn(b));
    H = pk2h(a, b);
    L = pk2h(a - ha, b - hb);
}

// ---------------- fp32 -> fp16 splits ----------------
__global__ __launch_bounds__(256) void cvt_x(const float* __restrict__ src,
                                             __half* __restrict__ p1, __half* __restrict__ p2) {
    size_t i = (size_t)blockIdx.x * 256 + threadIdx.x;
    float4 v = ((const float4*)src)[i];
    uint2 H, L;
    split2h(v.x, v.y, H.x, L.x);
    split2h(v.z, v.w, H.y, L.y);
    ((uint2*)p1)[i] = H;
    ((uint2*)p2)[i] = L;
}
__global__ __launch_bounds__(256) void cvt_w(const float* __restrict__ src,
                                             __half* __restrict__ p1) {
    size_t i = (size_t)blockIdx.x * 256 + threadIdx.x;
    float4 v = ((const float4*)src)[i];
    uint2 H;
    H.x = pk2h(v.x, v.y);
    H.y = pk2h(v.z, v.w);
    ((uint2*)p1)[i] = H;
}

// ================= fp16 2-pass GEMM: C = alpha*(A1+A2)(B1)^T, CTA 128x256 ===========
// 3-stage cp.async, K-step 64. Stage 64KB: A1 16KB @0, A2 16KB @16384, B1 32KB @32768.
#define KIT 32
#define STG_B 65536
#define GEMM_SMEM (3 * STG_B)   // 196608

__device__ __forceinline__ void issue_stage(uint32_t sbase,
        const __half* __restrict__ A1, const __half* __restrict__ A2,
        const __half* __restrict__ B1, int k0, int tid) {
    #pragma unroll
    for (int i = 0; i < 8; i++) {             // A: 2 planes x 128 rows x 8 chunks
        int idx = tid + i * 256;              // 0..2047
        int pl = idx >> 10, rem = idx & 1023;
        int row = rem >> 3, c = rem & 7;
        const __half* src = (pl ? A2 : A1) + (size_t)row * DD + k0 + c * 8;
        cp16(sbase + pl * 16384 + row * 128 + (((uint32_t)c ^ (row & 7)) << 4), src);
    }
    #pragma unroll
    for (int i = 0; i < 8; i++) {             // B: 256 rows x 8 chunks
        int idx = tid + i * 256;
        int row = idx >> 3, c = idx & 7;
        const __half* src = B1 + (size_t)row * DD + k0 + c * 8;
        cp16(sbase + 32768 + row * 128 + (((uint32_t)c ^ (row & 7)) << 4), src);
    }
    asm volatile("cp.async.commit_group;\n" ::: "memory");
}

__device__ __forceinline__ void stage_compute(uint32_t sbase, int lane,
                                              int wm0, int wn0, float acc[4][8][4]) {
    const int arow = (lane & 7) + ((lane >> 3) & 1) * 8;
    const int asel = lane >> 4;
    const int brow = (lane & 7) + ((lane >> 4) << 3);
    const int bsel = (lane >> 3) & 1;
    #pragma unroll
    for (int ks = 0; ks < 4; ks++) {
        uint32_t a1[4][4], a2[4][4];
        #pragma unroll
        for (int mf = 0; mf < 4; mf++) {
            int row = wm0 + mf * 16 + arow;
            int c = ks * 2 + asel;
            uint32_t off = row * 128 + (((uint32_t)c ^ (row & 7)) << 4);
            ldsm4(a1[mf], sbase + off);
            ldsm4(a2[mf], sbase + 16384 + off);
        }
        uint32_t b1[4][4];
        #pragma unroll
        for (int nq = 0; nq < 4; nq++) {
            int row = wn0 + nq * 16 + brow;
            int c = ks * 2 + bsel;
            ldsm4(b1[nq], sbase + 32768 + row * 128 + (((uint32_t)c ^ (row & 7)) << 4));
        }
        #pragma unroll
        for (int mf = 0; mf < 4; mf++)
            #pragma unroll
            for (int nf = 0; nf < 8; nf++) {
                const uint32_t* b = &b1[nf >> 1][(nf & 1) * 2];
                mma_f16(acc[mf][nf], a1[mf], b);
                mma_f16(acc[mf][nf], a2[mf], b);
            }
    }
}

// If Cf != null: fp32 output (grid.x = 8). Else fused QKV (grid.x = 24):
// proj 0 -> (Q1,Q2)*QSCALE ; proj 1 -> (K1,K2) ; proj 2 -> V1 (single plane).
__global__ __launch_bounds__(256, 1) void gemm_mma(
        const __half* __restrict__ A1, const __half* __restrict__ A2,
        const __half* __restrict__ B1,
        float* __restrict__ Cf,
        uint32_t* __restrict__ Q1, uint32_t* __restrict__ Q2,
        uint32_t* __restrict__ K1, uint32_t* __restrict__ K2,
        uint32_t* __restrict__ V1) {
    extern __shared__ char smc[];
    const uint32_t sb = smem_u32(smc);
    const int tid = threadIdx.x, lane = tid & 31, w = tid >> 5;
    const int bm0 = blockIdx.y * 128;
    const int bnG = blockIdx.x * 256;
    const int wm0 = (w >> 2) * 64, wn0 = (w & 3) * 64;
    const __half* At1 = A1 + (size_t)bm0 * DD;
    const __half* At2 = A2 + (size_t)bm0 * DD;
    const __half* Bt1 = B1 + (size_t)bnG * DD;

    float acc[4][8][4];
    #pragma unroll
    for (int a = 0; a < 4; a++)
        #pragma unroll
        for (int b = 0; b < 8; b++)
            #pragma unroll
            for (int c = 0; c < 4; c++) acc[a][b][c] = 0.f;

    issue_stage(sb + 0 * STG_B, At1, At2, Bt1, 0,   tid);
    issue_stage(sb + 1 * STG_B, At1, At2, Bt1, 64,  tid);
    issue_stage(sb + 2 * STG_B, At1, At2, Bt1, 128, tid);

    for (int it = 0; it < KIT; ++it) {
        if (it <= KIT - 3)      asm volatile("cp.async.wait_group 2;\n" ::: "memory");
        else if (it == KIT - 2) asm volatile("cp.async.wait_group 1;\n" ::: "memory");
        else                    asm volatile("cp.async.wait_group 0;\n" ::: "memory");
        __syncthreads();
        stage_compute(sb + (it % 3) * STG_B, lane, wm0, wn0, acc);
        __syncthreads();
        if (it + 3 < KIT)
            issue_stage(sb + (it % 3) * STG_B, At1, At2, Bt1, (it + 3) * 64, tid);
    }

    const int proj = bnG >> 11;
    const int ncol0 = bnG & 2047;
    const float alpha = (Cf == nullptr && proj == 0) ? QSCALE : 1.f;

    const int r0 = lane >> 2, c0 = lane & 3;
    #pragma unroll
    for (int mf = 0; mf < 4; mf++)
        #pragma unroll
        for (int nf = 0; nf < 8; nf++) {
            int row = bm0 + wm0 + mf * 16 + r0;
            int col = ncol0 + wn0 + nf * 8 + c0 * 2;
            float v0 = alpha * acc[mf][nf][0], v1 = alpha * acc[mf][nf][1];
            float v2 = alpha * acc[mf][nf][2], v3 = alpha * acc[mf][nf][3];
            if (Cf) {
                *(float2*)(Cf + (size_t)row * DD + col) = make_float2(v0, v1);
                *(float2*)(Cf + (size_t)(row + 8) * DD + col) = make_float2(v2, v3);
            } else {
                size_t pA = (size_t)row * (DD / 2) + (col >> 1);
                size_t pB = (size_t)(row + 8) * (DD / 2) + (col >> 1);
                if (proj == 2) {
                    V1[pA] = pk2h(v0, v1);
                    V1[pB] = pk2h(v2, v3);
                } else {
                    uint32_t* Ch = (proj == 0) ? Q1 : K1;
                    uint32_t* Cl = (proj == 0) ? Q2 : K2;
                    uint32_t H, L;
                    split2h(v0, v1, H, L); Ch[pA] = H; Cl[pA] = L;
                    split2h(v2, v3, H, L); Ch[pB] = H; Cl[pB] = L;
                }
            }
        }
}

// ================= kv: KV[d][e] = sum_s K[s][d] V[s][e] =================
#define KV_SMEM 49152   // k1 16KB @0, k2 @16384, v1 @32768
__global__ __launch_bounds__(256) void kv_mma(
        const __half* __restrict__ K1g, const __half* __restrict__ K2g,
        const __half* __restrict__ V1g, float* __restrict__ KV) {
    extern __shared__ char smc[];
    const uint32_t sb = smem_u32(smc);
    const int tid = threadIdx.x, lane = tid & 31, w = tid >> 5;
    const int blk = blockIdx.x;
    const int bh = blk / NC, cch = blk % NC;
    const int b = bh / HH, h = bh % HH;
    const size_t grow = (size_t)(b * SS + cch * CHUNK);

    const __half* tiles[3] = {K1g, K2g, V1g};
    #pragma unroll
    for (int i = 0; i < 12; i++) {
        int idx = tid + (i & 3) * 256;     // 0..1023
        int t3 = i >> 2;
        int row = idx >> 4, c = idx & 15;
        const __half* src = tiles[t3] + (grow + row) * DD + h * HD + c * 8;
        cp16(sb + t3 * 16384 + row * 256 + (((uint32_t)c ^ (row & 7)) << 4), src);
    }
    asm volatile("cp.async.commit_group;\ncp.async.wait_group 0;\n" ::: "memory");
    __syncthreads();

    const int md0 = (w >> 1) * 32, ne0 = (w & 1) * 64;
    const int j = lane & 7, g1 = (lane >> 3) & 1, g2 = lane >> 4;

    float acc[2][8][4];
    #pragma unroll
    for (int a = 0; a < 2; a++)
        #pragma unroll
        for (int n = 0; n < 8; n++)
            #pragma unroll
            for (int e = 0; e < 4; e++) acc[a][n][e] = 0.f;

    #pragma unroll
    for (int kb = 0; kb < 4; kb++) {
        uint32_t a1[2][4], a2[2][4];
        #pragma unroll
        for (int mf = 0; mf < 2; mf++) {
            int row = kb * 16 + g2 * 8 + j;
            int c = (md0 >> 3) + mf * 2 + g1;
            uint32_t off = row * 256 + (((uint32_t)c ^ (row & 7)) << 4);
            ldsm4t(a1[mf], sb + off);
            ldsm4t(a2[mf], sb + 16384 + off);
        }
        uint32_t v1[4][4];
        #pragma unroll
        for (int nf2 = 0; nf2 < 4; nf2++) {
            int row = kb * 16 + g1 * 8 + j;
            int c = (ne0 >> 3) + nf2 * 2 + g2;
            ldsm4t(v1[nf2], sb + 32768 + row * 256 + (((uint32_t)c ^ (row & 7)) << 4));
        }
        #pragma unroll
        for (int mf = 0; mf < 2; mf++)
            #pragma unroll
            for (int nf = 0; nf < 8; nf++) {
                const uint32_t* bb = &v1[nf >> 1][(nf & 1) * 2];
                mma_f16(acc[mf][nf], a1[mf], bb);
                mma_f16(acc[mf][nf], a2[mf], bb);
            }
    }
    float* out = KV + (size_t)blk * (HD * HD);
    const int r0 = lane >> 2, c0 = (lane & 3) * 2;
    #pragma unroll
    for (int mf = 0; mf < 2; mf++)
        #pragma unroll
        for (int nf = 0; nf < 8; nf++) {
            int d = md0 + mf * 16 + r0;
            int e = ne0 + nf * 8 + c0;
            *(float2*)(out + (size_t)d * HD + e) = make_float2(acc[mf][nf][0], acc[mf][nf][1]);
            *(float2*)(out + (size_t)(d + 8) * HD + e) = make_float2(acc[mf][nf][2], acc[mf][nf][3]);
        }
}

// ================= exclusive chunk scan: fp32 KV -> fp16 S =================
__global__ __launch_bounds__(256) void scan_kernel(const float* __restrict__ KV,
                                                   __half* __restrict__ S1) {
    size_t g = (size_t)blockIdx.x * 256 + threadIdx.x;
    int bh = (int)(g >> 13);
    int p  = (int)(g & 8191);
    const float2* src = (const float2*)(KV + (size_t)bh * NC * HD * HD) + p;
    uint32_t* dh = (uint32_t*)(S1 + (size_t)bh * NC * HD * HD) + p;
    float a0 = 0.f, a1 = 0.f;
    for (int c = 0; c < NC; c++) {
        float2 t = src[(size_t)c * 8192];
        dh[(size_t)c * 8192] = pk2h(a0, a1);
        a0 += t.x; a1 += t.y;
    }
}

// ================= attn: o = tril(q k^T) v + q S =================
#define ATTN_SMEM 98304
#define AQ1 0
#define AQ2 16384
#define AK1 32768
#define AV1 49152
#define AS1 65536

__global__ __launch_bounds__(256) void attn_mma(
        const __half* __restrict__ Q1g, const __half* __restrict__ Q2g,
        const __half* __restrict__ K1g, const __half* __restrict__ V1g,
        const __half* __restrict__ S1g,
        uint32_t* __restrict__ O1, uint32_t* __restrict__ O2) {
    extern __shared__ char smc[];
    const uint32_t sb = smem_u32(smc);
    const int tid = threadIdx.x, lane = tid & 31, w = tid >> 5;
    const int blk = blockIdx.x;
    const int bh = blk / NC, cch = blk % NC;
    const int b = bh / HH, h = bh % HH;
    const size_t grow = (size_t)(b * SS + cch * CHUNK);

    const __half* tiles[4] = {Q1g, Q2g, K1g, V1g};
    #pragma unroll
    for (int i = 0; i < 16; i++) {
        int t4 = i >> 2;
        int idx = tid + (i & 3) * 256;      // 0..1023
        int row = idx >> 4, c = idx & 15;
        const __half* src = tiles[t4] + (grow + row) * DD + h * HD + c * 8;
        cp16(sb + t4 * 16384 + row * 256 + (((uint32_t)c ^ (row & 7)) << 4), src);
    }
    const size_t sgb = (size_t)blk * (HD * HD);
    #pragma unroll
    for (int i = 0; i < 8; i++) {
        int idx = tid + i * 256;            // 0..2047
        int row = idx >> 4, c = idx & 15;
        const __half* src = S1g + sgb + (size_t)row * HD + c * 8;
        cp16(sb + AS1 + row * 256 + (((uint32_t)c ^ (row & 7)) << 4), src);
    }
    asm volatile("cp.async.commit_group;\ncp.async.wait_group 0;\n" ::: "memory");
    __syncthreads();

    const int mrow = (w >> 1) * 16, nh = w & 1;
    const int arow = (lane & 7) + ((lane >> 3) & 1) * 8;
    const int asel = lane >> 4;
    const int brow = (lane & 7) + ((lane >> 4) << 3);
    const int bsel = (lane >> 3) & 1;
    const int j = lane & 7, g1 = (lane >> 3) & 1, g2 = lane >> 4;

    // ---- qk^T ----
    float qk[8][4];
    #pragma unroll
    for (int n = 0; n < 8; n++)
        #pragma unroll
        for (int e = 0; e < 4; e++) qk[n][e] = 0.f;

    #pragma unroll
    for (int kb = 0; kb < 8; kb++) {
        uint32_t q1[4], q2[4];
        {
            int row = mrow + arow;
            int c = kb * 2 + asel;
            uint32_t off = row * 256 + (((uint32_t)c ^ (row & 7)) << 4);
            ldsm4(q1, sb + AQ1 + off);
            ldsm4(q2, sb + AQ2 + off);
        }
        uint32_t k1[4][4];
        #pragma unroll
        for (int nq = 0; nq < 4; nq++) {
            int row = nq * 16 + brow;
            int c = kb * 2 + bsel;
            ldsm4(k1[nq], sb + AK1 + row * 256 + (((uint32_t)c ^ (row & 7)) << 4));
        }
        #pragma unroll
        for (int nf = 0; nf < 8; nf++) {
            const uint32_t* bb = &k1[nf >> 1][(nf & 1) * 2];
            mma_f16(qk[nf], q1, bb);
            mma_f16(qk[nf], q2, bb);
        }
    }
    // ---- causal mask ----
    const int r0 = lane >> 2, c0 = (lane & 3) * 2;
    #pragma unroll
    for (int nf = 0; nf < 8; nf++)
        #pragma unroll
        for (int e = 0; e < 4; e++) {
            int rloc = mrow + r0 + ((e >= 2) ? 8 : 0);
            int scol = nf * 8 + c0 + (e & 1);
            if (scol > rloc) qk[nf][e] = 0.f;
        }

    float o[8][4];
    #pragma unroll
    for (int n = 0; n < 8; n++)
        #pragma unroll
        for (int e = 0; e < 4; e++) o[n][e] = 0.f;

    // ---- intra: o += attn @ V ----
    #pragma unroll
    for (int kb2 = 0; kb2 < 4; kb2++) {
        uint32_t Ah[4], Al[4];
        split2h(qk[2 * kb2][0],     qk[2 * kb2][1],     Ah[0], Al[0]);
        split2h(qk[2 * kb2][2],     qk[2 * kb2][3],     Ah[1], Al[1]);
        split2h(qk[2 * kb2 + 1][0], qk[2 * kb2 + 1][1], Ah[2], Al[2]);
        split2h(qk[2 * kb2 + 1][2], qk[2 * kb2 + 1][3], Ah[3], Al[3]);
        uint32_t v1[4][4];
        #pragma unroll
        for (int nf2 = 0; nf2 < 4; nf2++) {
            int row = kb2 * 16 + g1 * 8 + j;
            int c = nh * 8 + nf2 * 2 + g2;
            ldsm4t(v1[nf2], sb + AV1 + row * 256 + (((uint32_t)c ^ (row & 7)) << 4));
        }
        #pragma unroll
        for (int nf = 0; nf < 8; nf++) {
            const uint32_t* bb = &v1[nf >> 1][(nf & 1) * 2];
            mma_f16(o[nf], Ah, bb);
            mma_f16(o[nf], Al, bb);
        }
    }
    // ---- inter: o += q @ S ----
    #pragma unroll
    for (int kb = 0; kb < 8; kb++) {
        uint32_t q1[4], q2[4];
        {
            int row = mrow + arow;
            int c = kb * 2 + asel;
            uint32_t off = row * 256 + (((uint32_t)c ^ (row & 7)) << 4);
            ldsm4(q1, sb + AQ1 + off);
            ldsm4(q2, sb + AQ2 + off);
        }
        uint32_t s1[4][4];
        #pragma unroll
        for (int nf2 = 0; nf2 < 4; nf2++) {
            int row = kb * 16 + g1 * 8 + j;
            int c = nh * 8 + nf2 * 2 + g2;
            ldsm4t(s1[nf2], sb + AS1 + row * 256 + (((uint32_t)c ^ (row & 7)) << 4));
        }
        #pragma unroll
        for (int nf = 0; nf < 8; nf++) {
            const uint32_t* bb = &s1[nf >> 1][(nf & 1) * 2];
            mma_f16(o[nf], q1, bb);
            mma_f16(o[nf], q2, bb);
        }
    }
    // ---- epilogue: write o as fp16 hi/lo planes ----
    #pragma unroll
    for (int nf = 0; nf < 8; nf++) {
        int col = h * HD + nh * 64 + nf * 8 + c0;
        size_t pA = (grow + mrow + r0) * (DD / 2) + (col >> 1);
        size_t pB = (grow + mrow + r0 + 8) * (DD / 2) + (col >> 1);
        uint32_t H, L;
        split2h(o[nf][0], o[nf][1], H, L); O1[pA] = H; O2[pA] = L;
        split2h(o[nf][2], o[nf][3], H, L); O1[pB] = H; O2[pB] = L;
    }
}

// ---------------------------------------------------------------------------
extern "C" void kernel_launch(void* const* d_in, const int* in_sizes, int n_in,
                              void* d_out, int out_size) {
    const float* x  = (const float*)d_in[0];
    const float* Wq = (const float*)d_in[1];
    const float* Wk = (const float*)d_in[2];
    const float* Wv = (const float*)d_in[3];
    const float* Wo = (const float*)d_in[4];
    float* out = (float*)d_out;

    __half *px1, *px2, *pw1, *pq1, *pq2, *pk1, *pk2, *pv1, *po1, *po2, *pS1;
    float* pKV;
    cudaGetSymbolAddress((void**)&px1, g_x1);
    cudaGetSymbolAddress((void**)&px2, g_x2);
    cudaGetSymbolAddress((void**)&pw1, g_w1);
    cudaGetSymbolAddress((void**)&pq1, g_q1);
    cudaGetSymbolAddress((void**)&pq2, g_q2);
    cudaGetSymbolAddress((void**)&pk1, g_k1);
    cudaGetSymbolAddress((void**)&pk2, g_k2);
    cudaGetSymbolAddress((void**)&pv1, g_v1);
    cudaGetSymbolAddress((void**)&po1, g_o1);
    cudaGetSymbolAddress((void**)&po2, g_o2);
    cudaGetSymbolAddress((void**)&pS1, g_S1);
    cudaGetSymbolAddress((void**)&pKV, g_KV);

    cudaFuncSetAttribute(gemm_mma, cudaFuncAttributeMaxDynamicSharedMemorySize, GEMM_SMEM);
    cudaFuncSetAttribute(kv_mma,   cudaFuncAttributeMaxDynamicSharedMemorySize, KV_SMEM);
    cudaFuncSetAttribute(attn_mma, cudaFuncAttributeMaxDynamicSharedMemorySize, ATTN_SMEM);

    // splits: x -> 2 fp16 planes; each W -> 1 fp16 plane
    cvt_x<<<(MROWS * DD) / 1024, 256>>>(x, px1, px2);
    cvt_w<<<WSZ / 1024, 256>>>(Wq, pw1 + 0 * (size_t)WSZ);
    cvt_w<<<WSZ / 1024, 256>>>(Wk, pw1 + 1 * (size_t)WSZ);
    cvt_w<<<WSZ / 1024, 256>>>(Wv, pw1 + 2 * (size_t)WSZ);
    cvt_w<<<WSZ / 1024, 256>>>(Wo, pw1 + 3 * (size_t)WSZ);

    // fused Q,K,V projections (B = [Wq; Wk; Wv] contiguous in g_w1)
    dim3 qkvgrid(3 * DD / 256, MROWS / 128);   // (24, 64)
    gemm_mma<<<qkvgrid, 256, GEMM_SMEM>>>(px1, px2, pw1, nullptr,
                                          (uint32_t*)pq1, (uint32_t*)pq2,
                                          (uint32_t*)pk1, (uint32_t*)pk2,
                                          (uint32_t*)pv1);

    kv_mma<<<NBH * NC, 256, KV_SMEM>>>(pk1, pk2, pv1, pKV);
    scan_kernel<<<(NBH * 8192) / 256, 256>>>(pKV, pS1);
    attn_mma<<<NBH * NC, 256, ATTN_SMEM>>>(pq1, pq2, pk1, pv1, pS1,
                                           (uint32_t*)po1, (uint32_t*)po2);

    // output projection
    dim3 ogrid(DD / 256, MROWS / 128);         // (8, 64)
    gemm_mma<<<ogrid, 256, GEMM_SMEM>>>(po1, po2, pw1 + 3 * (size_t)WSZ, out,
                                        nullptr, nullptr, nullptr, nullptr, nullptr);

    (void)in_sizes; (void)n_in; (void)out_size;
}

// round 10
// speedup vs baseline: 1.7651x; 1.6717x over previous
#include <cuda_runtime.h>
#include <cuda_fp16.h>
#include <cstdint>

// ---------------- problem constants ----------------
#define BB   2
#define SS   4096
#define DD   2048
#define HH   16
#define HD   128
#define CHUNK 64
#define NC   64
#define MROWS 8192
#define NBH  32
#define QSCALE 0.08838834764831845f
#define WSZ  (DD * DD)

// ---------------- scratch (device globals) ----------------
__device__ __align__(256) __half g_x1[(size_t)MROWS * DD];
__device__ __align__(256) __half g_x2[(size_t)MROWS * DD];
__device__ __align__(256) __half g_w1[(size_t)4 * WSZ];
__device__ __align__(256) __half g_q1[(size_t)MROWS * DD];
__device__ __align__(256) __half g_q2[(size_t)MROWS * DD];
__device__ __align__(256) __half g_k1[(size_t)MROWS * DD];
__device__ __align__(256) __half g_k2[(size_t)MROWS * DD];
__device__ __align__(256) __half g_v1[(size_t)MROWS * DD];
__device__ __align__(256) __half g_o1[(size_t)MROWS * DD];
__device__ __align__(256) __half g_o2[(size_t)MROWS * DD];
__device__ float g_KV[(size_t)NBH * NC * HD * HD];
__device__ __align__(256) __half g_S1[(size_t)NBH * NC * HD * HD];

// ---------------- helpers ----------------
__device__ __forceinline__ uint32_t smem_u32(const void* p) {
    return (uint32_t)__cvta_generic_to_shared(p);
}
__device__ __forceinline__ void cp16(uint32_t d, const void* s) {
    asm volatile("cp.async.cg.shared.global [%0], [%1], 16;\n" :: "r"(d), "l"(s));
}
__device__ __forceinline__ void ldsm4(uint32_t* r, uint32_t a) {
    asm volatile("ldmatrix.sync.aligned.m8n8.x4.shared.b16 {%0,%1,%2,%3}, [%4];\n"
                 : "=r"(r[0]), "=r"(r[1]), "=r"(r[2]), "=r"(r[3]) : "r"(a));
}
__device__ __forceinline__ void ldsm4t(uint32_t* r, uint32_t a) {
    asm volatile("ldmatrix.sync.aligned.m8n8.x4.trans.shared.b16 {%0,%1,%2,%3}, [%4];\n"
                 : "=r"(r[0]), "=r"(r[1]), "=r"(r[2]), "=r"(r[3]) : "r"(a));
}
__device__ __forceinline__ void mma_f16(float* c, const uint32_t* a, const uint32_t* b) {
    asm volatile("mma.sync.aligned.m16n8k16.row.col.f32.f16.f16.f32 "
                 "{%0,%1,%2,%3}, {%4,%5,%6,%7}, {%8,%9}, {%0,%1,%2,%3};\n"
                 : "+f"(c[0]), "+f"(c[1]), "+f"(c[2]), "+f"(c[3])
                 : "r"(a[0]), "r"(a[1]), "r"(a[2]), "r"(a[3]), "r"(b[0]), "r"(b[1]));
}
__device__ __forceinline__ uint32_t pk2h(float a, float b) {
    __half2 t = __floats2half2_rn(a, b);
    return *(uint32_t*)&t;
}
__device__ __forceinline__ void split2h(float a, float b, uint32_t& H, uint32_t& L) {
    float ha = __half2float(__float2half_rn(a));
    float hb = __half2float(__float2half_rn(b));
    H = pk2h(a, b);
    L = pk2h(a - ha, b - hb);
}

// ---------------- fp32 -> fp16 splits ----------------
__global__ __launch_bounds__(256) void cvt_x(const float* __restrict__ src,
                                             __half* __restrict__ p1, __half* __restrict__ p2) {
    size_t i = (size_t)blockIdx.x * 256 + threadIdx.x;
    float4 v = ((const float4*)src)[i];
    uint2 H, L;
    split2h(v.x, v.y, H.x, L.x);
    split2h(v.z, v.w, H.y, L.y);
    ((uint2*)p1)[i] = H;
    ((uint2*)p2)[i] = L;
}
// all four weights in one launch: blockIdx.y selects the matrix
__global__ __launch_bounds__(256) void cvt_w4(const float* __restrict__ s0,
                                              const float* __restrict__ s1,
                                              const float* __restrict__ s2,
                                              const float* __restrict__ s3,
                                              __half* __restrict__ p1) {
    const float* src = (blockIdx.y == 0) ? s0 : (blockIdx.y == 1) ? s1
                     : (blockIdx.y == 2) ? s2 : s3;
    size_t i = (size_t)blockIdx.x * 256 + threadIdx.x;
    float4 v = ((const float4*)src)[i];
    uint2 H;
    H.x = pk2h(v.x, v.y);
    H.y = pk2h(v.z, v.w);
    ((uint2*)(p1 + (size_t)blockIdx.y * WSZ))[i] = H;
}

// ================= fp16 2-pass GEMM: C = alpha*(A1+A2)(B1)^T, CTA 128x128 ===========
// 2-stage cp.async, K-step 64, 2 CTAs/SM. Stage 48KB: A1 @0, A2 @16384, B1 @32768.
#define KIT 32
#define STG_B 49152
#define GEMM_SMEM (2 * STG_B)   // 98304 -> 2 CTAs per SM

__device__ __forceinline__ void issue_stage(uint32_t sbase,
        const __half* __restrict__ A1, const __half* __restrict__ A2,
        const __half* __restrict__ B1, int k0, int tid) {
    #pragma unroll
    for (int i = 0; i < 8; i++) {             // A: 2 planes x 128 rows x 8 chunks
        int idx = tid + i * 256;              // 0..2047
        int pl = idx >> 10, rem = idx & 1023;
        int row = rem >> 3, c = rem & 7;
        const __half* src = (pl ? A2 : A1) + (size_t)row * DD + k0 + c * 8;
        cp16(sbase + pl * 16384 + row * 128 + (((uint32_t)c ^ (row & 7)) << 4), src);
    }
    #pragma unroll
    for (int i = 0; i < 4; i++) {             // B: 128 rows x 8 chunks
        int idx = tid + i * 256;              // 0..1023
        int row = idx >> 3, c = idx & 7;
        const __half* src = B1 + (size_t)row * DD + k0 + c * 8;
        cp16(sbase + 32768 + row * 128 + (((uint32_t)c ^ (row & 7)) << 4), src);
    }
    asm volatile("cp.async.commit_group;\n" ::: "memory");
}

__device__ __forceinline__ void stage_compute(uint32_t sbase, int lane,
                                              int wm0, int wn0, float acc[4][4][4]) {
    const int arow = (lane & 7) + ((lane >> 3) & 1) * 8;
    const int asel = lane >> 4;
    const int brow = (lane & 7) + ((lane >> 4) << 3);
    const int bsel = (lane >> 3) & 1;
    #pragma unroll
    for (int ks = 0; ks < 4; ks++) {
        uint32_t a1[4][4], a2[4][4];
        #pragma unroll
        for (int mf = 0; mf < 4; mf++) {
            int row = wm0 + mf * 16 + arow;
            int c = ks * 2 + asel;
            uint32_t off = row * 128 + (((uint32_t)c ^ (row & 7)) << 4);
            ldsm4(a1[mf], sbase + off);
            ldsm4(a2[mf], sbase + 16384 + off);
        }
        uint32_t b1[2][4];
        #pragma unroll
        for (int nq = 0; nq < 2; nq++) {
            int row = wn0 + nq * 16 + brow;
            int c = ks * 2 + bsel;
            ldsm4(b1[nq], sbase + 32768 + row * 128 + (((uint32_t)c ^ (row & 7)) << 4));
        }
        #pragma unroll
        for (int mf = 0; mf < 4; mf++)
            #pragma unroll
            for (int nf = 0; nf < 4; nf++) {
                const uint32_t* b = &b1[nf >> 1][(nf & 1) * 2];
                mma_f16(acc[mf][nf], a1[mf], b);
                mma_f16(acc[mf][nf], a2[mf], b);
            }
    }
}

// If Cf != null: fp32 output (grid.x = 16). Else fused QKV (grid.x = 48):
// proj 0 -> (Q1,Q2)*QSCALE ; proj 1 -> (K1,K2) ; proj 2 -> V1 (single plane).
__global__ __launch_bounds__(256, 2) void gemm_mma(
        const __half* __restrict__ A1, const __half* __restrict__ A2,
        const __half* __restrict__ B1,
        float* __restrict__ Cf,
        uint32_t* __restrict__ Q1, uint32_t* __restrict__ Q2,
        uint32_t* __restrict__ K1, uint32_t* __restrict__ K2,
        uint32_t* __restrict__ V1) {
    extern __shared__ char smc[];
    const uint32_t sb = smem_u32(smc);
    const int tid = threadIdx.x, lane = tid & 31, w = tid >> 5;
    const int bm0 = blockIdx.y * 128;
    const int bnG = blockIdx.x * 128;
    const int wm0 = (w >> 2) * 64, wn0 = (w & 3) * 32;
    const __half* At1 = A1 + (size_t)bm0 * DD;
    const __half* At2 = A2 + (size_t)bm0 * DD;
    const __half* Bt1 = B1 + (size_t)bnG * DD;

    float acc[4][4][4];
    #pragma unroll
    for (int a = 0; a < 4; a++)
        #pragma unroll
        for (int b = 0; b < 4; b++)
            #pragma unroll
            for (int c = 0; c < 4; c++) acc[a][b][c] = 0.f;

    issue_stage(sb, At1, At2, Bt1, 0, tid);

    for (int it = 0; it < KIT; ++it) {
        if (it + 1 < KIT) {
            issue_stage(sb + ((it + 1) & 1) * STG_B, At1, At2, Bt1, (it + 1) * 64, tid);
            asm volatile("cp.async.wait_group 1;\n" ::: "memory");
        } else {
            asm volatile("cp.async.wait_group 0;\n" ::: "memory");
        }
        __syncthreads();
        stage_compute(sb + (it & 1) * STG_B, lane, wm0, wn0, acc);
        __syncthreads();
    }

    const int proj = bnG >> 11;
    const int ncol0 = bnG & 2047;
    const float alpha = (Cf == nullptr && proj == 0) ? QSCALE : 1.f;

    const int r0 = lane >> 2, c0 = lane & 3;
    #pragma unroll
    for (int mf = 0; mf < 4; mf++)
        #pragma unroll
        for (int nf = 0; nf < 4; nf++) {
            int row = bm0 + wm0 + mf * 16 + r0;
            int col = ncol0 + wn0 + nf * 8 + c0 * 2;
            float v0 = alpha * acc[mf][nf][0], v1 = alpha * acc[mf][nf][1];
            float v2 = alpha * acc[mf][nf][2], v3 = alpha * acc[mf][nf][3];
            if (Cf) {
                *(float2*)(Cf + (size_t)row * DD + col) = make_float2(v0, v1);
                *(float2*)(Cf + (size_t)(row + 8) * DD + col) = make_float2(v2, v3);
            } else {
                size_t pA = (size_t)row * (DD / 2) + (col >> 1);
                size_t pB = (size_t)(row + 8) * (DD / 2) + (col >> 1);
                if (proj == 2) {
                    V1[pA] = pk2h(v0, v1);
                    V1[pB] = pk2h(v2, v3);
                } else {
                    uint32_t* Ch = (proj == 0) ? Q1 : K1;
                    uint32_t* Cl = (proj == 0) ? Q2 : K2;
                    uint32_t H, L;
                    split2h(v0, v1, H, L); Ch[pA] = H; Cl[pA] = L;
                    split2h(v2, v3, H, L); Ch[pB] = H; Cl[pB] = L;
                }
            }
        }
}

// ================= kv: KV[d][e] = sum_s K[s][d] V[s][e] =================
#define KV_SMEM 49152   // k1 16KB @0, k2 @16384, v1 @32768
__global__ __launch_bounds__(256) void kv_mma(
        const __half* __restrict__ K1g, const __half* __restrict__ K2g,
        const __half* __restrict__ V1g, float* __restrict__ KV) {
    extern __shared__ char smc[];
    const uint32_t sb = smem_u32(smc);
    const int tid = threadIdx.x, lane = tid & 31, w = tid >> 5;
    const int blk = blockIdx.x;
    const int bh = blk / NC, cch = blk % NC;
    const int b = bh / HH, h = bh % HH;
    const size_t grow = (size_t)(b * SS + cch * CHUNK);

    const __half* tiles[3] = {K1g, K2g, V1g};
    #pragma unroll
    for (int i = 0; i < 12; i++) {
        int idx = tid + (i & 3) * 256;     // 0..1023
        int t3 = i >> 2;
        int row = idx >> 4, c = idx & 15;
        const __half* src = tiles[t3] + (grow + row) * DD + h * HD + c * 8;
        cp16(sb + t3 * 16384 + row * 256 + (((uint32_t)c ^ (row & 7)) << 4), src);
    }
    asm volatile("cp.async.commit_group;\ncp.async.wait_group 0;\n" ::: "memory");
    __syncthreads();

    const int md0 = (w >> 1) * 32, ne0 = (w & 1) * 64;
    const int j = lane & 7, g1 = (lane >> 3) & 1, g2 = lane >> 4;

    float acc[2][8][4];
    #pragma unroll
    for (int a = 0; a < 2; a++)
        #pragma unroll
        for (int n = 0; n < 8; n++)
            #pragma unroll
            for (int e = 0; e < 4; e++) acc[a][n][e] = 0.f;

    #pragma unroll
    for (int kb = 0; kb < 4; kb++) {
        uint32_t a1[2][4], a2[2][4];
        #pragma unroll
        for (int mf = 0; mf < 2; mf++) {
            int row = kb * 16 + g2 * 8 + j;
            int c = (md0 >> 3) + mf * 2 + g1;
            uint32_t off = row * 256 + (((uint32_t)c ^ (row & 7)) << 4);
            ldsm4t(a1[mf], sb + off);
            ldsm4t(a2[mf], sb + 16384 + off);
        }
        uint32_t v1[4][4];
        #pragma unroll
        for (int nf2 = 0; nf2 < 4; nf2++) {
            int row = kb * 16 + g1 * 8 + j;
            int c = (ne0 >> 3) + nf2 * 2 + g2;
            ldsm4t(v1[nf2], sb + 32768 + row * 256 + (((uint32_t)c ^ (row & 7)) << 4));
        }
        #pragma unroll
        for (int mf = 0; mf < 2; mf++)
            #pragma unroll
            for (int nf = 0; nf < 8; nf++) {
                const uint32_t* bb = &v1[nf >> 1][(nf & 1) * 2];
                mma_f16(acc[mf][nf], a1[mf], bb);
                mma_f16(acc[mf][nf], a2[mf], bb);
            }
    }
    float* out = KV + (size_t)blk * (HD * HD);
    const int r0 = lane >> 2, c0 = (lane & 3) * 2;
    #pragma unroll
    for (int mf = 0; mf < 2; mf++)
        #pragma unroll
        for (int nf = 0; nf < 8; nf++) {
            int d = md0 + mf * 16 + r0;
            int e = ne0 + nf * 8 + c0;
            *(float2*)(out + (size_t)d * HD + e) = make_float2(acc[mf][nf][0], acc[mf][nf][1]);
            *(float2*)(out + (size_t)(d + 8) * HD + e) = make_float2(acc[mf][nf][2], acc[mf][nf][3]);
        }
}

// ================= exclusive chunk scan: fp32 KV -> fp16 S =================
__global__ __launch_bounds__(256) void scan_kernel(const float* __restrict__ KV,
                                                   __half* __restrict__ S1) {
    size_t g = (size_t)blockIdx.x * 256 + threadIdx.x;
    int bh = (int)(g >> 13);
    int p  = (int)(g & 8191);
    const float2* src = (const float2*)(KV + (size_t)bh * NC * HD * HD) + p;
    uint32_t* dh = (uint32_t*)(S1 + (size_t)bh * NC * HD * HD) + p;
    float a0 = 0.f, a1 = 0.f;
    for (int c = 0; c < NC; c++) {
        float2 t = src[(size_t)c * 8192];
        dh[(size_t)c * 8192] = pk2h(a0, a1);
        a0 += t.x; a1 += t.y;
    }
}

// ================= attn: o = tril(q k^T) v + q S =================
#define ATTN_SMEM 98304
#define AQ1 0
#define AQ2 16384
#define AK1 32768
#define AV1 49152
#define AS1 65536

__global__ __launch_bounds__(256) void attn_mma(
        const __half* __restrict__ Q1g, const __half* __restrict__ Q2g,
        const __half* __restrict__ K1g, const __half* __restrict__ V1g,
        const __half* __restrict__ S1g,
        uint32_t* __restrict__ O1, uint32_t* __restrict__ O2) {
    extern __shared__ char smc[];
    const uint32_t sb = smem_u32(smc);
    const int tid = threadIdx.x, lane = tid & 31, w = tid >> 5;
    const int blk = blockIdx.x;
    const int bh = blk / NC, cch = blk % NC;
    const int b = bh / HH, h = bh % HH;
    const size_t grow = (size_t)(b * SS + cch * CHUNK);

    const __half* tiles[4] = {Q1g, Q2g, K1g, V1g};
    #pragma unroll
    for (int i = 0; i < 16; i++) {
        int t4 = i >> 2;
        int idx = tid + (i & 3) * 256;      // 0..1023
        int row = idx >> 4, c = idx & 15;
        const __half* src = tiles[t4] + (grow + row) * DD + h * HD + c * 8;
        cp16(sb + t4 * 16384 + row * 256 + (((uint32_t)c ^ (row & 7)) << 4), src);
    }
    const size_t sgb = (size_t)blk * (HD * HD);
    #pragma unroll
    for (int i = 0; i < 8; i++) {
        int idx = tid + i * 256;            // 0..2047
        int row = idx >> 4, c = idx & 15;
        const __half* src = S1g + sgb + (size_t)row * HD + c * 8;
        cp16(sb + AS1 + row * 256 + (((uint32_t)c ^ (row & 7)) << 4), src);
    }
    asm volatile("cp.async.commit_group;\ncp.async.wait_group 0;\n" ::: "memory");
    __syncthreads();

    const int mrow = (w >> 1) * 16, nh = w & 1;
    const int arow = (lane & 7) + ((lane >> 3) & 1) * 8;
    const int asel = lane >> 4;
    const int brow = (lane & 7) + ((lane >> 4) << 3);
    const int bsel = (lane >> 3) & 1;
    const int j = lane & 7, g1 = (lane >> 3) & 1, g2 = lane >> 4;

    // ---- qk^T ----
    float qk[8][4];
    #pragma unroll
    for (int n = 0; n < 8; n++)
        #pragma unroll
        for (int e = 0; e < 4; e++) qk[n][e] = 0.f;

    #pragma unroll
    for (int kb = 0; kb < 8; kb++) {
        uint32_t q1[4], q2[4];
        {
            int row = mrow + arow;
            int c = kb * 2 + asel;
            uint32_t off = row * 256 + (((uint32_t)c ^ (row & 7)) << 4);
            ldsm4(q1, sb + AQ1 + off);
            ldsm4(q2, sb + AQ2 + off);
        }
        uint32_t k1[4][4];
        #pragma unroll
        for (int nq = 0; nq < 4; nq++) {
            int row = nq * 16 + brow;
            int c = kb * 2 + bsel;
            ldsm4(k1[nq], sb + AK1 + row * 256 + (((uint32_t)c ^ (row & 7)) << 4));
        }
        #pragma unroll
        for (int nf = 0; nf < 8; nf++) {
            const uint32_t* bb = &k1[nf >> 1][(nf & 1) * 2];
            mma_f16(qk[nf], q1, bb);
            mma_f16(qk[nf], q2, bb);
        }
    }
    // ---- causal mask ----
    const int r0 = lane >> 2, c0 = (lane & 3) * 2;
    #pragma unroll
    for (int nf = 0; nf < 8; nf++)
        #pragma unroll
        for (int e = 0; e < 4; e++) {
            int rloc = mrow + r0 + ((e >= 2) ? 8 : 0);
            int scol = nf * 8 + c0 + (e & 1);
            if (scol > rloc) qk[nf][e] = 0.f;
        }

    float o[8][4];
    #pragma unroll
    for (int n = 0; n < 8; n++)
        #pragma unroll
        for (int e = 0; e < 4; e++) o[n][e] = 0.f;

    // ---- intra: o += attn @ V ----
    #pragma unroll
    for (int kb2 = 0; kb2 < 4; kb2++) {
        uint32_t Ah[4], Al[4];
        split2h(qk[2 * kb2][0],     qk[2 * kb2][1],     Ah[0], Al[0]);
        split2h(qk[2 * kb2][2],     qk[2 * kb2][3],     Ah[1], Al[1]);
        split2h(qk[2 * kb2 + 1][0], qk[2 * kb2 + 1][1], Ah[2], Al[2]);
        split2h(qk[2 * kb2 + 1][2], qk[2 * kb2 + 1][3], Ah[3], Al[3]);
        uint32_t v1[4][4];
        #pragma unroll
        for (int nf2 = 0; nf2 < 4; nf2++) {
            int row = kb2 * 16 + g1 * 8 + j;
            int c = nh * 8 + nf2 * 2 + g2;
            ldsm4t(v1[nf2], sb + AV1 + row * 256 + (((uint32_t)c ^ (row & 7)) << 4));
        }
        #pragma unroll
        for (int nf = 0; nf < 8; nf++) {
            const uint32_t* bb = &v1[nf >> 1][(nf & 1) * 2];
            mma_f16(o[nf], Ah, bb);
            mma_f16(o[nf], Al, bb);
        }
    }
    // ---- inter: o += q @ S ----
    #pragma unroll
    for (int kb = 0; kb < 8; kb++) {
        uint32_t q1[4], q2[4];
        {
            int row = mrow + arow;
            int c = kb * 2 + asel;
            uint32_t off = row * 256 + (((uint32_t)c ^ (row & 7)) << 4);
            ldsm4(q1, sb + AQ1 + off);
            ldsm4(q2, sb + AQ2 + off);
        }
        uint32_t s1[4][4];
        #pragma unroll
        for (int nf2 = 0; nf2 < 4; nf2++) {
            int row = kb * 16 + g1 * 8 + j;
            int c = nh * 8 + nf2 * 2 + g2;
            ldsm4t(s1[nf2], sb + AS1 + row * 256 + (((uint32_t)c ^ (row & 7)) << 4));
        }
        #pragma unroll
        for (int nf = 0; nf < 8; nf++) {
            const uint32_t* bb = &s1[nf >> 1][(nf & 1) * 2];
            mma_f16(o[nf], q1, bb);
            mma_f16(o[nf], q2, bb);
        }
    }
    // ---- epilogue: write o as fp16 hi/lo planes ----
    #pragma unroll
    for (int nf = 0; nf < 8; nf++) {
        int col = h * HD + nh * 64 + nf * 8 + c0;
        size_t pA = (grow + mrow + r0) * (DD / 2) + (col >> 1);
        size_t pB = (grow + mrow + r0 + 8) * (DD / 2) + (col >> 1);
        uint32_t H, L;
        split2h(o[nf][0], o[nf][1], H, L); O1[pA] = H; O2[pA] = L;
        split2h(o[nf][2], o[nf][3], H, L); O1[pB] = H; O2[pB] = L;
    }
}

// ---------------------------------------------------------------------------
extern "C" void kernel_launch(void* const* d_in, const int* in_sizes, int n_in,
                              void* d_out, int out_size) {
    const float* x  = (const float*)d_in[0];
    const float* Wq = (const float*)d_in[1];
    const float* Wk = (const float*)d_in[2];
    const float* Wv = (const float*)d_in[3];
    const float* Wo = (const float*)d_in[4];
    float* out = (float*)d_out;

    __half *px1, *px2, *pw1, *pq1, *pq2, *pk1, *pk2, *pv1, *po1, *po2, *pS1;
    float* pKV;
    cudaGetSymbolAddress((void**)&px1, g_x1);
    cudaGetSymbolAddress((void**)&px2, g_x2);
    cudaGetSymbolAddress((void**)&pw1, g_w1);
    cudaGetSymbolAddress((void**)&pq1, g_q1);
    cudaGetSymbolAddress((void**)&pq2, g_q2);
    cudaGetSymbolAddress((void**)&pk1, g_k1);
    cudaGetSymbolAddress((void**)&pk2, g_k2);
    cudaGetSymbolAddress((void**)&pv1, g_v1);
    cudaGetSymbolAddress((void**)&po1, g_o1);
    cudaGetSymbolAddress((void**)&po2, g_o2);
    cudaGetSymbolAddress((void**)&pS1, g_S1);
    cudaGetSymbolAddress((void**)&pKV, g_KV);

    cudaFuncSetAttribute(gemm_mma, cudaFuncAttributeMaxDynamicSharedMemorySize, GEMM_SMEM);
    cudaFuncSetAttribute(kv_mma,   cudaFuncAttributeMaxDynamicSharedMemorySize, KV_SMEM);
    cudaFuncSetAttribute(attn_mma, cudaFuncAttributeMaxDynamicSharedMemorySize, ATTN_SMEM);

    // splits: x -> 2 fp16 planes; all W -> 1 fp16 plane (single launch)
    cvt_x<<<(MROWS * DD) / 1024, 256>>>(x, px1, px2);
    dim3 wgrid(WSZ / 1024, 4);
    cvt_w4<<<wgrid, 256>>>(Wq, Wk, Wv, Wo, pw1);

    // fused Q,K,V projections (B = [Wq; Wk; Wv] contiguous in g_w1)
    dim3 qkvgrid(3 * DD / 128, MROWS / 128);   // (48, 64)
    gemm_mma<<<qkvgrid, 256, GEMM_SMEM>>>(px1, px2, pw1, nullptr,
                                          (uint32_t*)pq1, (uint32_t*)pq2,
                                          (uint32_t*)pk1, (uint32_t*)pk2,
                                          (uint32_t*)pv1);

    kv_mma<<<NBH * NC, 256, KV_SMEM>>>(pk1, pk2, pv1, pKV);
    scan_kernel<<<(NBH * 8192) / 256, 256>>>(pKV, pS1);
    attn_mma<<<NBH * NC, 256, ATTN_SMEM>>>(pq1, pq2, pk1, pv1, pS1,
                                           (uint32_t*)po1, (uint32_t*)po2);

    // output projection
    dim3 ogrid(DD / 128, MROWS / 128);         // (16, 64)
    gemm_mma<<<ogrid, 256, GEMM_SMEM>>>(po1, po2, pw1 + 3 * (size_t)WSZ, out,
                                        nullptr, nullptr, nullptr, nullptr, nullptr);

    (void)in_sizes; (void)n_in; (void)out_size;
}

// round 11
// speedup vs baseline: 1.7947x; 1.0167x over previous
#include <cuda_runtime.h>
#include <cuda_fp16.h>
#include <cstdint>

// ---------------- problem constants ----------------
#define BB   2
#define SS   4096
#define DD   2048
#define HH   16
#define HD   128
#define CHUNK 64
#define NC   64
#define MROWS 8192
#define NBH  32
#define QSCALE 0.08838834764831845f
#define WSZ  (DD * DD)

// ---------------- scratch (device globals) ----------------
__device__ __align__(256) __half g_x1[(size_t)MROWS * DD];
__device__ __align__(256) __half g_x2[(size_t)MROWS * DD];
__device__ __align__(256) __half g_w1[(size_t)4 * WSZ];
__device__ __align__(256) __half g_q1[(size_t)MROWS * DD];
__device__ __align__(256) __half g_q2[(size_t)MROWS * DD];
__device__ __align__(256) __half g_k1[(size_t)MROWS * DD];
__device__ __align__(256) __half g_k2[(size_t)MROWS * DD];
__device__ __align__(256) __half g_v1[(size_t)MROWS * DD];
__device__ __align__(256) __half g_o1[(size_t)MROWS * DD];
__device__ float g_KV[(size_t)NBH * NC * HD * HD];
__device__ __align__(256) __half g_S1[(size_t)NBH * NC * HD * HD];

// ---------------- helpers ----------------
__device__ __forceinline__ uint32_t smem_u32(const void* p) {
    return (uint32_t)__cvta_generic_to_shared(p);
}
__device__ __forceinline__ void cp16(uint32_t d, const void* s) {
    asm volatile("cp.async.cg.shared.global [%0], [%1], 16;\n" :: "r"(d), "l"(s));
}
__device__ __forceinline__ void ldsm4(uint32_t* r, uint32_t a) {
    asm volatile("ldmatrix.sync.aligned.m8n8.x4.shared.b16 {%0,%1,%2,%3}, [%4];\n"
                 : "=r"(r[0]), "=r"(r[1]), "=r"(r[2]), "=r"(r[3]) : "r"(a));
}
__device__ __forceinline__ void ldsm4t(uint32_t* r, uint32_t a) {
    asm volatile("ldmatrix.sync.aligned.m8n8.x4.trans.shared.b16 {%0,%1,%2,%3}, [%4];\n"
                 : "=r"(r[0]), "=r"(r[1]), "=r"(r[2]), "=r"(r[3]) : "r"(a));
}
__device__ __forceinline__ void mma_f16(float* c, const uint32_t* a, const uint32_t* b) {
    asm volatile("mma.sync.aligned.m16n8k16.row.col.f32.f16.f16.f32 "
                 "{%0,%1,%2,%3}, {%4,%5,%6,%7}, {%8,%9}, {%0,%1,%2,%3};\n"
                 : "+f"(c[0]), "+f"(c[1]), "+f"(c[2]), "+f"(c[3])
                 : "r"(a[0]), "r"(a[1]), "r"(a[2]), "r"(a[3]), "r"(b[0]), "r"(b[1]));
}
__device__ __forceinline__ uint32_t pk2h(float a, float b) {
    __half2 t = __floats2half2_rn(a, b);
    return *(uint32_t*)&t;
}
__device__ __forceinline__ void split2h(float a, float b, uint32_t& H, uint32_t& L) {
    float ha = __half2float(__float2half_rn(a));
    float hb = __half2float(__float2half_rn(b));
    H = pk2h(a, b);
    L = pk2h(a - ha, b - hb);
}

// ---------------- fp32 -> fp16 splits ----------------
__global__ __launch_bounds__(256) void cvt_x(const float* __restrict__ src,
                                             __half* __restrict__ p1, __half* __restrict__ p2) {
    size_t i = (size_t)blockIdx.x * 256 + threadIdx.x;
    float4 v = ((const float4*)src)[i];
    uint2 H, L;
    split2h(v.x, v.y, H.x, L.x);
    split2h(v.z, v.w, H.y, L.y);
    ((uint2*)p1)[i] = H;
    ((uint2*)p2)[i] = L;
}
// all four weights in one launch: blockIdx.y selects the matrix
__global__ __launch_bounds__(256) void cvt_w4(const float* __restrict__ s0,
                                              const float* __restrict__ s1,
                                              const float* __restrict__ s2,
                                              const float* __restrict__ s3,
                                              __half* __restrict__ p1) {
    const float* src = (blockIdx.y == 0) ? s0 : (blockIdx.y == 1) ? s1
                     : (blockIdx.y == 2) ? s2 : s3;
    size_t i = (size_t)blockIdx.x * 256 + threadIdx.x;
    float4 v = ((const float4*)src)[i];
    uint2 H;
    H.x = pk2h(v.x, v.y);
    H.y = pk2h(v.z, v.w);
    ((uint2*)(p1 + (size_t)blockIdx.y * WSZ))[i] = H;
}

// ================= fp16 GEMM: C = alpha*(A1[+A2])(B1)^T, CTA 128x128, occ 2 =========
// 2-stage cp.async, K-step 64. Stage 48KB: A1 @0, A2 @16384, B1 @32768.
// np = 1 or 2 passes (uniform per CTA; single-pass skips A2 loads + mmas).
#define KIT 32
#define STG_B 49152
#define GEMM_SMEM (2 * STG_B)   // 98304 -> 2 CTAs per SM

__device__ __forceinline__ void issue_stage(uint32_t sbase,
        const __half* __restrict__ A1, const __half* __restrict__ A2,
        const __half* __restrict__ B1, int k0, int tid, int np) {
    #pragma unroll
    for (int i = 0; i < 4; i++) {             // A1: 128 rows x 8 chunks
        int idx = tid + i * 256;              // 0..1023
        int row = idx >> 3, c = idx & 7;
        const __half* src = A1 + (size_t)row * DD + k0 + c * 8;
        cp16(sbase + row * 128 + (((uint32_t)c ^ (row & 7)) << 4), src);
    }
    if (np == 2) {
        #pragma unroll
        for (int i = 0; i < 4; i++) {         // A2: 128 rows x 8 chunks
            int idx = tid + i * 256;
            int row = idx >> 3, c = idx & 7;
            const __half* src = A2 + (size_t)row * DD + k0 + c * 8;
            cp16(sbase + 16384 + row * 128 + (((uint32_t)c ^ (row & 7)) << 4), src);
        }
    }
    #pragma unroll
    for (int i = 0; i < 4; i++) {             // B: 128 rows x 8 chunks
        int idx = tid + i * 256;              // 0..1023
        int row = idx >> 3, c = idx & 7;
        const __half* src = B1 + (size_t)row * DD + k0 + c * 8;
        cp16(sbase + 32768 + row * 128 + (((uint32_t)c ^ (row & 7)) << 4), src);
    }
    asm volatile("cp.async.commit_group;\n" ::: "memory");
}

__device__ __forceinline__ void stage_compute(uint32_t sbase, int lane,
                                              int wm0, int wn0, float acc[4][4][4],
                                              int np) {
    const int arow = (lane & 7) + ((lane >> 3) & 1) * 8;
    const int asel = lane >> 4;
    const int brow = (lane & 7) + ((lane >> 4) << 3);
    const int bsel = (lane >> 3) & 1;
    #pragma unroll
    for (int ks = 0; ks < 4; ks++) {
        uint32_t a1[4][4], a2[4][4];
        #pragma unroll
        for (int mf = 0; mf < 4; mf++) {
            int row = wm0 + mf * 16 + arow;
            int c = ks * 2 + asel;
            uint32_t off = row * 128 + (((uint32_t)c ^ (row & 7)) << 4);
            ldsm4(a1[mf], sbase + off);
            if (np == 2) ldsm4(a2[mf], sbase + 16384 + off);
        }
        uint32_t b1[2][4];
        #pragma unroll
        for (int nq = 0; nq < 2; nq++) {
            int row = wn0 + nq * 16 + brow;
            int c = ks * 2 + bsel;
            ldsm4(b1[nq], sbase + 32768 + row * 128 + (((uint32_t)c ^ (row & 7)) << 4));
        }
        #pragma unroll
        for (int mf = 0; mf < 4; mf++)
            #pragma unroll
            for (int nf = 0; nf < 4; nf++) {
                const uint32_t* b = &b1[nf >> 1][(nf & 1) * 2];
                mma_f16(acc[mf][nf], a1[mf], b);
                if (np == 2) mma_f16(acc[mf][nf], a2[mf], b);
            }
    }
}

// If Cf != null: fp32 output, single-pass (grid.x = 16). Else fused QKV (grid.x = 48):
// proj 0 -> (Q1,Q2)*QSCALE 2-pass ; proj 1 -> (K1,K2) 2-pass ; proj 2 -> V1 1-pass.
__global__ __launch_bounds__(256, 2) void gemm_mma(
        const __half* __restrict__ A1, const __half* __restrict__ A2,
        const __half* __restrict__ B1,
        float* __restrict__ Cf,
        uint32_t* __restrict__ Q1, uint32_t* __restrict__ Q2,
        uint32_t* __restrict__ K1, uint32_t* __restrict__ K2,
        uint32_t* __restrict__ V1) {
    extern __shared__ char smc[];
    const uint32_t sb = smem_u32(smc);
    const int tid = threadIdx.x, lane = tid & 31, w = tid >> 5;
    const int bm0 = blockIdx.y * 128;
    const int bnG = blockIdx.x * 128;
    const int wm0 = (w >> 2) * 64, wn0 = (w & 3) * 32;
    const int proj = (Cf == nullptr) ? (bnG >> 11) : 3;
    const int np = (Cf != nullptr || proj == 2) ? 1 : 2;
    const __half* At1 = A1 + (size_t)bm0 * DD;
    const __half* At2 = A2 + (size_t)bm0 * DD;
    const __half* Bt1 = B1 + (size_t)bnG * DD;

    float acc[4][4][4];
    #pragma unroll
    for (int a = 0; a < 4; a++)
        #pragma unroll
        for (int b = 0; b < 4; b++)
            #pragma unroll
            for (int c = 0; c < 4; c++) acc[a][b][c] = 0.f;

    issue_stage(sb, At1, At2, Bt1, 0, tid, np);

    for (int it = 0; it < KIT; ++it) {
        if (it + 1 < KIT) {
            issue_stage(sb + ((it + 1) & 1) * STG_B, At1, At2, Bt1, (it + 1) * 64, tid, np);
            asm volatile("cp.async.wait_group 1;\n" ::: "memory");
        } else {
            asm volatile("cp.async.wait_group 0;\n" ::: "memory");
        }
        __syncthreads();
        stage_compute(sb + (it & 1) * STG_B, lane, wm0, wn0, acc, np);
        __syncthreads();
    }

    const int ncol0 = bnG & 2047;
    const float alpha = (Cf == nullptr && proj == 0) ? QSCALE : 1.f;

    const int r0 = lane >> 2, c0 = lane & 3;
    #pragma unroll
    for (int mf = 0; mf < 4; mf++)
        #pragma unroll
        for (int nf = 0; nf < 4; nf++) {
            int row = bm0 + wm0 + mf * 16 + r0;
            int col = ncol0 + wn0 + nf * 8 + c0 * 2;
            float v0 = alpha * acc[mf][nf][0], v1 = alpha * acc[mf][nf][1];
            float v2 = alpha * acc[mf][nf][2], v3 = alpha * acc[mf][nf][3];
            if (Cf) {
                *(float2*)(Cf + (size_t)row * DD + col) = make_float2(v0, v1);
                *(float2*)(Cf + (size_t)(row + 8) * DD + col) = make_float2(v2, v3);
            } else {
                size_t pA = (size_t)row * (DD / 2) + (col >> 1);
                size_t pB = (size_t)(row + 8) * (DD / 2) + (col >> 1);
                if (proj == 2) {
                    V1[pA] = pk2h(v0, v1);
                    V1[pB] = pk2h(v2, v3);
                } else {
                    uint32_t* Ch = (proj == 0) ? Q1 : K1;
                    uint32_t* Cl = (proj == 0) ? Q2 : K2;
                    uint32_t H, L;
                    split2h(v0, v1, H, L); Ch[pA] = H; Cl[pA] = L;
                    split2h(v2, v3, H, L); Ch[pB] = H; Cl[pB] = L;
                }
            }
        }
}

// ================= kv: KV[d][e] = sum_s K[s][d] V[s][e] =================
#define KV_SMEM 49152   // k1 16KB @0, k2 @16384, v1 @32768
__global__ __launch_bounds__(256, 2) void kv_mma(
        const __half* __restrict__ K1g, const __half* __restrict__ K2g,
        const __half* __restrict__ V1g, float* __restrict__ KV) {
    extern __shared__ char smc[];
    const uint32_t sb = smem_u32(smc);
    const int tid = threadIdx.x, lane = tid & 31, w = tid >> 5;
    const int blk = blockIdx.x;
    const int bh = blk / NC, cch = blk % NC;
    const int b = bh / HH, h = bh % HH;
    const size_t grow = (size_t)(b * SS + cch * CHUNK);

    const __half* tiles[3] = {K1g, K2g, V1g};
    #pragma unroll
    for (int i = 0; i < 12; i++) {
        int idx = tid + (i & 3) * 256;     // 0..1023
        int t3 = i >> 2;
        int row = idx >> 4, c = idx & 15;
        const __half* src = tiles[t3] + (grow + row) * DD + h * HD + c * 8;
        cp16(sb + t3 * 16384 + row * 256 + (((uint32_t)c ^ (row & 7)) << 4), src);
    }
    asm volatile("cp.async.commit_group;\ncp.async.wait_group 0;\n" ::: "memory");
    __syncthreads();

    const int md0 = (w >> 1) * 32, ne0 = (w & 1) * 64;
    const int j = lane & 7, g1 = (lane >> 3) & 1, g2 = lane >> 4;

    float acc[2][8][4];
    #pragma unroll
    for (int a = 0; a < 2; a++)
        #pragma unroll
        for (int n = 0; n < 8; n++)
            #pragma unroll
            for (int e = 0; e < 4; e++) acc[a][n][e] = 0.f;

    #pragma unroll
    for (int kb = 0; kb < 4; kb++) {
        uint32_t a1[2][4], a2[2][4];
        #pragma unroll
        for (int mf = 0; mf < 2; mf++) {
            int row = kb * 16 + g2 * 8 + j;
            int c = (md0 >> 3) + mf * 2 + g1;
            uint32_t off = row * 256 + (((uint32_t)c ^ (row & 7)) << 4);
            ldsm4t(a1[mf], sb + off);
            ldsm4t(a2[mf], sb + 16384 + off);
        }
        uint32_t v1[4][4];
        #pragma unroll
        for (int nf2 = 0; nf2 < 4; nf2++) {
            int row = kb * 16 + g1 * 8 + j;
            int c = (ne0 >> 3) + nf2 * 2 + g2;
            ldsm4t(v1[nf2], sb + 32768 + row * 256 + (((uint32_t)c ^ (row & 7)) << 4));
        }
        #pragma unroll
        for (int mf = 0; mf < 2; mf++)
            #pragma unroll
            for (int nf = 0; nf < 8; nf++) {
                const uint32_t* bb = &v1[nf >> 1][(nf & 1) * 2];
                mma_f16(acc[mf][nf], a1[mf], bb);
                mma_f16(acc[mf][nf], a2[mf], bb);
            }
    }
    float* out = KV + (size_t)blk * (HD * HD);
    const int r0 = lane >> 2, c0 = (lane & 3) * 2;
    #pragma unroll
    for (int mf = 0; mf < 2; mf++)
        #pragma unroll
        for (int nf = 0; nf < 8; nf++) {
            int d = md0 + mf * 16 + r0;
            int e = ne0 + nf * 8 + c0;
            *(float2*)(out + (size_t)d * HD + e) = make_float2(acc[mf][nf][0], acc[mf][nf][1]);
            *(float2*)(out + (size_t)(d + 8) * HD + e) = make_float2(acc[mf][nf][2], acc[mf][nf][3]);
        }
}

// ================= exclusive chunk scan: fp32 KV -> fp16 S =================
__global__ __launch_bounds__(256) void scan_kernel(const float* __restrict__ KV,
                                                   __half* __restrict__ S1) {
    size_t g = (size_t)blockIdx.x * 256 + threadIdx.x;
    int bh = (int)(g >> 13);
    int p  = (int)(g & 8191);
    const float2* src = (const float2*)(KV + (size_t)bh * NC * HD * HD) + p;
    uint32_t* dh = (uint32_t*)(S1 + (size_t)bh * NC * HD * HD) + p;
    float a0 = 0.f, a1 = 0.f;
    for (int c = 0; c < NC; c++) {
        float2 t = src[(size_t)c * 8192];
        dh[(size_t)c * 8192] = pk2h(a0, a1);
        a0 += t.x; a1 += t.y;
    }
}

// ================= attn: o = tril(q k^T) v + q S =================
#define ATTN_SMEM 98304
#define AQ1 0
#define AQ2 16384
#define AK1 32768
#define AV1 49152
#define AS1 65536

__global__ __launch_bounds__(256, 2) void attn_mma(
        const __half* __restrict__ Q1g, const __half* __restrict__ Q2g,
        const __half* __restrict__ K1g, const __half* __restrict__ V1g,
        const __half* __restrict__ S1g,
        uint32_t* __restrict__ O1) {
    extern __shared__ char smc[];
    const uint32_t sb = smem_u32(smc);
    const int tid = threadIdx.x, lane = tid & 31, w = tid >> 5;
    const int blk = blockIdx.x;
    const int bh = blk / NC, cch = blk % NC;
    const int b = bh / HH, h = bh % HH;
    const size_t grow = (size_t)(b * SS + cch * CHUNK);

    const __half* tiles[4] = {Q1g, Q2g, K1g, V1g};
    #pragma unroll
    for (int i = 0; i < 16; i++) {
        int t4 = i >> 2;
        int idx = tid + (i & 3) * 256;      // 0..1023
        int row = idx >> 4, c = idx & 15;
        const __half* src = tiles[t4] + (grow + row) * DD + h * HD + c * 8;
        cp16(sb + t4 * 16384 + row * 256 + (((uint32_t)c ^ (row & 7)) << 4), src);
    }
    const size_t sgb = (size_t)blk * (HD * HD);
    #pragma unroll
    for (int i = 0; i < 8; i++) {
        int idx = tid + i * 256;            // 0..2047
        int row = idx >> 4, c = idx & 15;
        const __half* src = S1g + sgb + (size_t)row * HD + c * 8;
        cp16(sb + AS1 + row * 256 + (((uint32_t)c ^ (row & 7)) << 4), src);
    }
    asm volatile("cp.async.commit_group;\ncp.async.wait_group 0;\n" ::: "memory");
    __syncthreads();

    const int mrow = (w >> 1) * 16, nh = w & 1;
    const int arow = (lane & 7) + ((lane >> 3) & 1) * 8;
    const int asel = lane >> 4;
    const int brow = (lane & 7) + ((lane >> 4) << 3);
    const int bsel = (lane >> 3) & 1;
    const int j = lane & 7, g1 = (lane >> 3) & 1, g2 = lane >> 4;

    // ---- qk^T ----
    float qk[8][4];
    #pragma unroll
    for (int n = 0; n < 8; n++)
        #pragma unroll
        for (int e = 0; e < 4; e++) qk[n][e] = 0.f;

    #pragma unroll
    for (int kb = 0; kb < 8; kb++) {
        uint32_t q1[4], q2[4];
        {
            int row = mrow + arow;
            int c = kb * 2 + asel;
            uint32_t off = row * 256 + (((uint32_t)c ^ (row & 7)) << 4);
            ldsm4(q1, sb + AQ1 + off);
            ldsm4(q2, sb + AQ2 + off);
        }
        uint32_t k1[4][4];
        #pragma unroll
        for (int nq = 0; nq < 4; nq++) {
            int row = nq * 16 + brow;
            int c = kb * 2 + bsel;
            ldsm4(k1[nq], sb + AK1 + row * 256 + (((uint32_t)c ^ (row & 7)) << 4));
        }
        #pragma unroll
        for (int nf = 0; nf < 8; nf++) {
            const uint32_t* bb = &k1[nf >> 1][(nf & 1) * 2];
            mma_f16(qk[nf], q1, bb);
            mma_f16(qk[nf], q2, bb);
        }
    }
    // ---- causal mask ----
    const int r0 = lane >> 2, c0 = (lane & 3) * 2;
    #pragma unroll
    for (int nf = 0; nf < 8; nf++)
        #pragma unroll
        for (int e = 0; e < 4; e++) {
            int rloc = mrow + r0 + ((e >= 2) ? 8 : 0);
            int scol = nf * 8 + c0 + (e & 1);
            if (scol > rloc) qk[nf][e] = 0.f;
        }

    float o[8][4];
    #pragma unroll
    for (int n = 0; n < 8; n++)
        #pragma unroll
        for (int e = 0; e < 4; e++) o[n][e] = 0.f;

    // ---- intra: o += attn @ V ----
    #pragma unroll
    for (int kb2 = 0; kb2 < 4; kb2++) {
        uint32_t Ah[4], Al[4];
        split2h(qk[2 * kb2][0],     qk[2 * kb2][1],     Ah[0], Al[0]);
        split2h(qk[2 * kb2][2],     qk[2 * kb2][3],     Ah[1], Al[1]);
        split2h(qk[2 * kb2 + 1][0], qk[2 * kb2 + 1][1], Ah[2], Al[2]);
        split2h(qk[2 * kb2 + 1][2], qk[2 * kb2 + 1][3], Ah[3], Al[3]);
        uint32_t v1[4][4];
        #pragma unroll
        for (int nf2 = 0; nf2 < 4; nf2++) {
            int row = kb2 * 16 + g1 * 8 + j;
            int c = nh * 8 + nf2 * 2 + g2;
            ldsm4t(v1[nf2], sb + AV1 + row * 256 + (((uint32_t)c ^ (row & 7)) << 4));
        }
        #pragma unroll
        for (int nf = 0; nf < 8; nf++) {
            const uint32_t* bb = &v1[nf >> 1][(nf & 1) * 2];
            mma_f16(o[nf], Ah, bb);
            mma_f16(o[nf], Al, bb);
        }
    }
    // ---- inter: o += q @ S ----
    #pragma unroll
    for (int kb = 0; kb < 8; kb++) {
        uint32_t q1[4], q2[4];
        {
            int row = mrow + arow;
            int c = kb * 2 + asel;
            uint32_t off = row * 256 + (((uint32_t)c ^ (row & 7)) << 4);
            ldsm4(q1, sb + AQ1 + off);
            ldsm4(q2, sb + AQ2 + off);
        }
        uint32_t s1[4][4];
        #pragma unroll
        for (int nf2 = 0; nf2 < 4; nf2++) {
            int row = kb * 16 + g1 * 8 + j;
            int c = nh * 8 + nf2 * 2 + g2;
            ldsm4t(s1[nf2], sb + AS1 + row * 256 + (((uint32_t)c ^ (row & 7)) << 4));
        }
        #pragma unroll
        for (int nf = 0; nf < 8; nf++) {
            const uint32_t* bb = &s1[nf >> 1][(nf & 1) * 2];
            mma_f16(o[nf], q1, bb);
            mma_f16(o[nf], q2, bb);
        }
    }
    // ---- epilogue: write o as single fp16 plane ----
    #pragma unroll
    for (int nf = 0; nf < 8; nf++) {
        int col = h * HD + nh * 64 + nf * 8 + c0;
        size_t pA = (grow + mrow + r0) * (DD / 2) + (col >> 1);
        size_t pB = (grow + mrow + r0 + 8) * (DD / 2) + (col >> 1);
        O1[pA] = pk2h(o[nf][0], o[nf][1]);
        O1[pB] = pk2h(o[nf][2], o[nf][3]);
    }
}

// ---------------------------------------------------------------------------
extern "C" void kernel_launch(void* const* d_in, const int* in_sizes, int n_in,
                              void* d_out, int out_size) {
    const float* x  = (const float*)d_in[0];
    const float* Wq = (const float*)d_in[1];
    const float* Wk = (const float*)d_in[2];
    const float* Wv = (const float*)d_in[3];
    const float* Wo = (const float*)d_in[4];
    float* out = (float*)d_out;

    __half *px1, *px2, *pw1, *pq1, *pq2, *pk1, *pk2, *pv1, *po1, *pS1;
    float* pKV;
    cudaGetSymbolAddress((void**)&px1, g_x1);
    cudaGetSymbolAddress((void**)&px2, g_x2);
    cudaGetSymbolAddress((void**)&pw1, g_w1);
    cudaGetSymbolAddress((void**)&pq1, g_q1);
    cudaGetSymbolAddress((void**)&pq2, g_q2);
    cudaGetSymbolAddress((void**)&pk1, g_k1);
    cudaGetSymbolAddress((void**)&pk2, g_k2);
    cudaGetSymbolAddress((void**)&pv1, g_v1);
    cudaGetSymbolAddress((void**)&po1, g_o1);
    cudaGetSymbolAddress((void**)&pS1, g_S1);
    cudaGetSymbolAddress((void**)&pKV, g_KV);

    cudaFuncSetAttribute(gemm_mma, cudaFuncAttributeMaxDynamicSharedMemorySize, GEMM_SMEM);
    cudaFuncSetAttribute(kv_mma,   cudaFuncAttributeMaxDynamicSharedMemorySize, KV_SMEM);
    cudaFuncSetAttribute(attn_mma, cudaFuncAttributeMaxDynamicSharedMemorySize, ATTN_SMEM);

    // splits: x -> 2 fp16 planes; all W -> 1 fp16 plane (single launch)
    cvt_x<<<(MROWS * DD) / 1024, 256>>>(x, px1, px2);
    dim3 wgrid(WSZ / 1024, 4);
    cvt_w4<<<wgrid, 256>>>(Wq, Wk, Wv, Wo, pw1);

    // fused Q,K,V projections (B = [Wq; Wk; Wv] contiguous in g_w1)
    dim3 qkvgrid(3 * DD / 128, MROWS / 128);   // (48, 64)
    gemm_mma<<<qkvgrid, 256, GEMM_SMEM>>>(px1, px2, pw1, nullptr,
                                          (uint32_t*)pq1, (uint32_t*)pq2,
                                          (uint32_t*)pk1, (uint32_t*)pk2,
                                          (uint32_t*)pv1);

    kv_mma<<<NBH * NC, 256, KV_SMEM>>>(pk1, pk2, pv1, pKV);
    scan_kernel<<<(NBH * 8192) / 256, 256>>>(pKV, pS1);
    attn_mma<<<NBH * NC, 256, ATTN_SMEM>>>(pq1, pq2, pk1, pv1, pS1,
                                           (uint32_t*)po1);

    // output projection (single-pass fp16)
    dim3 ogrid(DD / 128, MROWS / 128);         // (16, 64)
    gemm_mma<<<ogrid, 256, GEMM_SMEM>>>(po1, po1, pw1 + 3 * (size_t)WSZ, out,
                                        nullptr, nullptr, nullptr, nullptr, nullptr);

    (void)in_sizes; (void)n_in; (void)out_size;
}

// round 12
// speedup vs baseline: 3.1771x; 1.7703x over previous
#include <cuda_runtime.h>
#include <cuda_fp16.h>
#include <cstdint>

// ---------------- problem constants ----------------
#define BB   2
#define SS   4096
#define DD   2048
#define HH   16
#define HD   128
#define CHUNK 64
#define NC   64
#define MROWS 8192
#define NBH  32
#define QSCALE 0.08838834764831845f
#define WSZ  (DD * DD)

// ---------------- scratch (device globals) ----------------
__device__ __align__(256) __half g_x1[(size_t)MROWS * DD];
__device__ __align__(256) __half g_w1[(size_t)4 * WSZ];
__device__ __align__(256) __half g_q1[(size_t)MROWS * DD];
__device__ __align__(256) __half g_k1[(size_t)MROWS * DD];
__device__ __align__(256) __half g_v1[(size_t)MROWS * DD];
__device__ __align__(256) __half g_o1[(size_t)MROWS * DD];
__device__ __align__(256) __half g_KV[(size_t)NBH * NC * HD * HD];
__device__ __align__(256) __half g_S1[(size_t)NBH * NC * HD * HD];

// ---------------- helpers ----------------
__device__ __forceinline__ uint32_t smem_u32(const void* p) {
    return (uint32_t)__cvta_generic_to_shared(p);
}
__device__ __forceinline__ void cp16(uint32_t d, const void* s) {
    asm volatile("cp.async.cg.shared.global [%0], [%1], 16;\n" :: "r"(d), "l"(s));
}
__device__ __forceinline__ void ldsm4(uint32_t* r, uint32_t a) {
    asm volatile("ldmatrix.sync.aligned.m8n8.x4.shared.b16 {%0,%1,%2,%3}, [%4];\n"
                 : "=r"(r[0]), "=r"(r[1]), "=r"(r[2]), "=r"(r[3]) : "r"(a));
}
__device__ __forceinline__ void ldsm4t(uint32_t* r, uint32_t a) {
    asm volatile("ldmatrix.sync.aligned.m8n8.x4.trans.shared.b16 {%0,%1,%2,%3}, [%4];\n"
                 : "=r"(r[0]), "=r"(r[1]), "=r"(r[2]), "=r"(r[3]) : "r"(a));
}
__device__ __forceinline__ void mma_f16(float* c, const uint32_t* a, const uint32_t* b) {
    asm volatile("mma.sync.aligned.m16n8k16.row.col.f32.f16.f16.f32 "
                 "{%0,%1,%2,%3}, {%4,%5,%6,%7}, {%8,%9}, {%0,%1,%2,%3};\n"
                 : "+f"(c[0]), "+f"(c[1]), "+f"(c[2]), "+f"(c[3])
                 : "r"(a[0]), "r"(a[1]), "r"(a[2]), "r"(a[3]), "r"(b[0]), "r"(b[1]));
}
__device__ __forceinline__ uint32_t pk2h(float a, float b) {
    __half2 t = __floats2half2_rn(a, b);
    return *(uint32_t*)&t;
}
__device__ __forceinline__ void split2h(float a, float b, uint32_t& H, uint32_t& L) {
    float ha = __half2float(__float2half_rn(a));
    float hb = __half2float(__float2half_rn(b));
    H = pk2h(a, b);
    L = pk2h(a - ha, b - hb);
}

// ---------------- fp32 -> fp16 convert ----------------
__global__ __launch_bounds__(256) void cvt1(const float* __restrict__ src,
                                            __half* __restrict__ p1) {
    size_t i = (size_t)blockIdx.x * 256 + threadIdx.x;
    float4 v = ((const float4*)src)[i];
    uint2 H;
    H.x = pk2h(v.x, v.y);
    H.y = pk2h(v.z, v.w);
    ((uint2*)p1)[i] = H;
}
__global__ __launch_bounds__(256) void cvt_w4(const float* __restrict__ s0,
                                              const float* __restrict__ s1,
                                              const float* __restrict__ s2,
                                              const float* __restrict__ s3,
                                              __half* __restrict__ p1) {
    const float* src = (blockIdx.y == 0) ? s0 : (blockIdx.y == 1) ? s1
                     : (blockIdx.y == 2) ? s2 : s3;
    size_t i = (size_t)blockIdx.x * 256 + threadIdx.x;
    float4 v = ((const float4*)src)[i];
    uint2 H;
    H.x = pk2h(v.x, v.y);
    H.y = pk2h(v.z, v.w);
    ((uint2*)(p1 + (size_t)blockIdx.y * WSZ))[i] = H;
}

// ================= fp16 single-pass GEMM: C = alpha*A1 B1^T, CTA 128x128, occ 2 =====
// 2-stage cp.async, K-step 64. Stage 32KB: A1 @0, B1 @16384.
#define KIT 32
#define STG_B 32768
#define GEMM_SMEM (2 * STG_B)   // 65536 -> 2 CTAs per SM

__device__ __forceinline__ void issue_stage(uint32_t sbase,
        const __half* __restrict__ A1, const __half* __restrict__ B1,
        int k0, int tid) {
    #pragma unroll
    for (int i = 0; i < 4; i++) {             // A1: 128 rows x 8 chunks
        int idx = tid + i * 256;              // 0..1023
        int row = idx >> 3, c = idx & 7;
        const __half* src = A1 + (size_t)row * DD + k0 + c * 8;
        cp16(sbase + row * 128 + (((uint32_t)c ^ (row & 7)) << 4), src);
    }
    #pragma unroll
    for (int i = 0; i < 4; i++) {             // B1: 128 rows x 8 chunks
        int idx = tid + i * 256;
        int row = idx >> 3, c = idx & 7;
        const __half* src = B1 + (size_t)row * DD + k0 + c * 8;
        cp16(sbase + 16384 + row * 128 + (((uint32_t)c ^ (row & 7)) << 4), src);
    }
    asm volatile("cp.async.commit_group;\n" ::: "memory");
}

__device__ __forceinline__ void stage_compute(uint32_t sbase, int lane,
                                              int wm0, int wn0, float acc[4][4][4]) {
    const int arow = (lane & 7) + ((lane >> 3) & 1) * 8;
    const int asel = lane >> 4;
    const int brow = (lane & 7) + ((lane >> 4) << 3);
    const int bsel = (lane >> 3) & 1;
    #pragma unroll
    for (int ks = 0; ks < 4; ks++) {
        uint32_t a1[4][4];
        #pragma unroll
        for (int mf = 0; mf < 4; mf++) {
            int row = wm0 + mf * 16 + arow;
            int c = ks * 2 + asel;
            ldsm4(a1[mf], sbase + row * 128 + (((uint32_t)c ^ (row & 7)) << 4));
        }
        uint32_t b1[2][4];
        #pragma unroll
        for (int nq = 0; nq < 2; nq++) {
            int row = wn0 + nq * 16 + brow;
            int c = ks * 2 + bsel;
            ldsm4(b1[nq], sbase + 16384 + row * 128 + (((uint32_t)c ^ (row & 7)) << 4));
        }
        #pragma unroll
        for (int mf = 0; mf < 4; mf++)
            #pragma unroll
            for (int nf = 0; nf < 4; nf++) {
                const uint32_t* b = &b1[nf >> 1][(nf & 1) * 2];
                mma_f16(acc[mf][nf], a1[mf], b);
            }
    }
}

// If Cf != null: fp32 output (grid.x = 16). Else fused QKV (grid.x = 48):
// proj 0 -> Q1*QSCALE ; proj 1 -> K1 ; proj 2 -> V1 (all single fp16 planes).
__global__ __launch_bounds__(256, 2) void gemm_mma(
        const __half* __restrict__ A1, const __half* __restrict__ B1,
        float* __restrict__ Cf,
        uint32_t* __restrict__ Q1, uint32_t* __restrict__ K1,
        uint32_t* __restrict__ V1) {
    extern __shared__ char smc[];
    const uint32_t sb = smem_u32(smc);
    const int tid = threadIdx.x, lane = tid & 31, w = tid >> 5;
    const int bm0 = blockIdx.y * 128;
    const int bnG = blockIdx.x * 128;
    const int wm0 = (w >> 2) * 64, wn0 = (w & 3) * 32;
    const __half* At1 = A1 + (size_t)bm0 * DD;
    const __half* Bt1 = B1 + (size_t)bnG * DD;

    float acc[4][4][4];
    #pragma unroll
    for (int a = 0; a < 4; a++)
        #pragma unroll
        for (int b = 0; b < 4; b++)
            #pragma unroll
            for (int c = 0; c < 4; c++) acc[a][b][c] = 0.f;

    issue_stage(sb, At1, Bt1, 0, tid);

    for (int it = 0; it < KIT; ++it) {
        if (it + 1 < KIT) {
            issue_stage(sb + ((it + 1) & 1) * STG_B, At1, Bt1, (it + 1) * 64, tid);
            asm volatile("cp.async.wait_group 1;\n" ::: "memory");
        } else {
            asm volatile("cp.async.wait_group 0;\n" ::: "memory");
        }
        __syncthreads();
        stage_compute(sb + (it & 1) * STG_B, lane, wm0, wn0, acc);
        __syncthreads();
    }

    const int proj = (Cf == nullptr) ? (bnG >> 11) : 3;
    const int ncol0 = bnG & 2047;
    const float alpha = (proj == 0) ? QSCALE : 1.f;

    const int r0 = lane >> 2, c0 = lane & 3;
    #pragma unroll
    for (int mf = 0; mf < 4; mf++)
        #pragma unroll
        for (int nf = 0; nf < 4; nf++) {
            int row = bm0 + wm0 + mf * 16 + r0;
            int col = ncol0 + wn0 + nf * 8 + c0 * 2;
            float v0 = alpha * acc[mf][nf][0], v1 = alpha * acc[mf][nf][1];
            float v2 = alpha * acc[mf][nf][2], v3 = alpha * acc[mf][nf][3];
            if (Cf) {
                *(float2*)(Cf + (size_t)row * DD + col) = make_float2(v0, v1);
                *(float2*)(Cf + (size_t)(row + 8) * DD + col) = make_float2(v2, v3);
            } else {
                size_t pA = (size_t)row * (DD / 2) + (col >> 1);
                size_t pB = (size_t)(row + 8) * (DD / 2) + (col >> 1);
                uint32_t* Cp = (proj == 0) ? Q1 : (proj == 1) ? K1 : V1;
                Cp[pA] = pk2h(v0, v1);
                Cp[pB] = pk2h(v2, v3);
            }
        }
}

// ================= kv: KV[d][e] = sum_s K[s][d] V[s][e]  (fp16 out) =================
#define KV_SMEM 32768   // k1 16KB @0, v1 @16384
__global__ __launch_bounds__(256, 2) void kv_mma(
        const __half* __restrict__ K1g, const __half* __restrict__ V1g,
        uint32_t* __restrict__ KV) {
    extern __shared__ char smc[];
    const uint32_t sb = smem_u32(smc);
    const int tid = threadIdx.x, lane = tid & 31, w = tid >> 5;
    const int blk = blockIdx.x;
    const int bh = blk / NC, cch = blk % NC;
    const int b = bh / HH, h = bh % HH;
    const size_t grow = (size_t)(b * SS + cch * CHUNK);

    const __half* tiles[2] = {K1g, V1g};
    #pragma unroll
    for (int i = 0; i < 8; i++) {
        int idx = tid + (i & 3) * 256;     // 0..1023
        int t2 = i >> 2;
        int row = idx >> 4, c = idx & 15;
        const __half* src = tiles[t2] + (grow + row) * DD + h * HD + c * 8;
        cp16(sb + t2 * 16384 + row * 256 + (((uint32_t)c ^ (row & 7)) << 4), src);
    }
    asm volatile("cp.async.commit_group;\ncp.async.wait_group 0;\n" ::: "memory");
    __syncthreads();

    const int md0 = (w >> 1) * 32, ne0 = (w & 1) * 64;
    const int j = lane & 7, g1 = (lane >> 3) & 1, g2 = lane >> 4;

    float acc[2][8][4];
    #pragma unroll
    for (int a = 0; a < 2; a++)
        #pragma unroll
        for (int n = 0; n < 8; n++)
            #pragma unroll
            for (int e = 0; e < 4; e++) acc[a][n][e] = 0.f;

    #pragma unroll
    for (int kb = 0; kb < 4; kb++) {
        uint32_t a1[2][4];
        #pragma unroll
        for (int mf = 0; mf < 2; mf++) {
            int row = kb * 16 + g2 * 8 + j;
            int c = (md0 >> 3) + mf * 2 + g1;
            ldsm4t(a1[mf], sb + row * 256 + (((uint32_t)c ^ (row & 7)) << 4));
        }
        uint32_t v1[4][4];
        #pragma unroll
        for (int nf2 = 0; nf2 < 4; nf2++) {
            int row = kb * 16 + g1 * 8 + j;
            int c = (ne0 >> 3) + nf2 * 2 + g2;
            ldsm4t(v1[nf2], sb + 16384 + row * 256 + (((uint32_t)c ^ (row & 7)) << 4));
        }
        #pragma unroll
        for (int mf = 0; mf < 2; mf++)
            #pragma unroll
            for (int nf = 0; nf < 8; nf++) {
                const uint32_t* bb = &v1[nf >> 1][(nf & 1) * 2];
                mma_f16(acc[mf][nf], a1[mf], bb);
            }
    }
    uint32_t* out = KV + (size_t)blk * (HD * HD / 2);
    const int r0 = lane >> 2, c0 = (lane & 3) * 2;
    #pragma unroll
    for (int mf = 0; mf < 2; mf++)
        #pragma unroll
        for (int nf = 0; nf < 8; nf++) {
            int d = md0 + mf * 16 + r0;
            int e = ne0 + nf * 8 + c0;
            out[(size_t)d * (HD / 2) + (e >> 1)] = pk2h(acc[mf][nf][0], acc[mf][nf][1]);
            out[(size_t)(d + 8) * (HD / 2) + (e >> 1)] = pk2h(acc[mf][nf][2], acc[mf][nf][3]);
        }
}

// ================= exclusive chunk scan: fp16 KV -> fp16 S (fp32 accum) =============
__global__ __launch_bounds__(256) void scan_kernel(const uint32_t* __restrict__ KV,
                                                   uint32_t* __restrict__ S1) {
    size_t g = (size_t)blockIdx.x * 256 + threadIdx.x;
    int bh = (int)(g >> 13);
    int p  = (int)(g & 8191);
    const uint32_t* src = KV + (size_t)bh * NC * 8192 + p;
    uint32_t* dst = S1 + (size_t)bh * NC * 8192 + p;
    float a0 = 0.f, a1 = 0.f;
    for (int c = 0; c < NC; c++) {
        uint32_t tv = src[(size_t)c * 8192];
        __half2 th = *(__half2*)&tv;
        float2 t = __half22float2(th);
        dst[(size_t)c * 8192] = pk2h(a0, a1);
        a0 += t.x; a1 += t.y;
    }
}

// ================= attn: o = tril(q k^T) v + q S =================
#define ATTN_SMEM 81920
#define AQ1 0
#define AK1 16384
#define AV1 32768
#define AS1 49152

__global__ __launch_bounds__(256, 2) void attn_mma(
        const __half* __restrict__ Q1g, const __half* __restrict__ K1g,
        const __half* __restrict__ V1g, const __half* __restrict__ S1g,
        uint32_t* __restrict__ O1) {
    extern __shared__ char smc[];
    const uint32_t sb = smem_u32(smc);
    const int tid = threadIdx.x, lane = tid & 31, w = tid >> 5;
    const int blk = blockIdx.x;
    const int bh = blk / NC, cch = blk % NC;
    const int b = bh / HH, h = bh % HH;
    const size_t grow = (size_t)(b * SS + cch * CHUNK);

    const __half* tiles[3] = {Q1g, K1g, V1g};
    #pragma unroll
    for (int i = 0; i < 12; i++) {
        int t3 = i >> 2;
        int idx = tid + (i & 3) * 256;      // 0..1023
        int row = idx >> 4, c = idx & 15;
        const __half* src = tiles[t3] + (grow + row) * DD + h * HD + c * 8;
        cp16(sb + t3 * 16384 + row * 256 + (((uint32_t)c ^ (row & 7)) << 4), src);
    }
    const size_t sgb = (size_t)blk * (HD * HD);
    #pragma unroll
    for (int i = 0; i < 8; i++) {
        int idx = tid + i * 256;            // 0..2047
        int row = idx >> 4, c = idx & 15;
        const __half* src = S1g + sgb + (size_t)row * HD + c * 8;
        cp16(sb + AS1 + row * 256 + (((uint32_t)c ^ (row & 7)) << 4), src);
    }
    asm volatile("cp.async.commit_group;\ncp.async.wait_group 0;\n" ::: "memory");
    __syncthreads();

    const int mrow = (w >> 1) * 16, nh = w & 1;
    const int arow = (lane & 7) + ((lane >> 3) & 1) * 8;
    const int asel = lane >> 4;
    const int brow = (lane & 7) + ((lane >> 4) << 3);
    const int bsel = (lane >> 3) & 1;
    const int j = lane & 7, g1 = (lane >> 3) & 1, g2 = lane >> 4;

    // ---- qk^T ----
    float qk[8][4];
    #pragma unroll
    for (int n = 0; n < 8; n++)
        #pragma unroll
        for (int e = 0; e < 4; e++) qk[n][e] = 0.f;

    #pragma unroll
    for (int kb = 0; kb < 8; kb++) {
        uint32_t q1[4];
        {
            int row = mrow + arow;
            int c = kb * 2 + asel;
            ldsm4(q1, sb + AQ1 + row * 256 + (((uint32_t)c ^ (row & 7)) << 4));
        }
        uint32_t k1[4][4];
        #pragma unroll
        for (int nq = 0; nq < 4; nq++) {
            int row = nq * 16 + brow;
            int c = kb * 2 + bsel;
            ldsm4(k1[nq], sb + AK1 + row * 256 + (((uint32_t)c ^ (row & 7)) << 4));
        }
        #pragma unroll
        for (int nf = 0; nf < 8; nf++) {
            const uint32_t* bb = &k1[nf >> 1][(nf & 1) * 2];
            mma_f16(qk[nf], q1, bb);
        }
    }
    // ---- causal mask ----
    const int r0 = lane >> 2, c0 = (lane & 3) * 2;
    #pragma unroll
    for (int nf = 0; nf < 8; nf++)
        #pragma unroll
        for (int e = 0; e < 4; e++) {
            int rloc = mrow + r0 + ((e >= 2) ? 8 : 0);
            int scol = nf * 8 + c0 + (e & 1);
            if (scol > rloc) qk[nf][e] = 0.f;
        }

    float o[8][4];
    #pragma unroll
    for (int n = 0; n < 8; n++)
        #pragma unroll
        for (int e = 0; e < 4; e++) o[n][e] = 0.f;

    // ---- intra: o += attn @ V  (2-pass register split of attn) ----
    #pragma unroll
    for (int kb2 = 0; kb2 < 4; kb2++) {
        uint32_t Ah[4], Al[4];
        split2h(qk[2 * kb2][0],     qk[2 * kb2][1],     Ah[0], Al[0]);
        split2h(qk[2 * kb2][2],     qk[2 * kb2][3],     Ah[1], Al[1]);
        split2h(qk[2 * kb2 + 1][0], qk[2 * kb2 + 1][1], Ah[2], Al[2]);
        split2h(qk[2 * kb2 + 1][2], qk[2 * kb2 + 1][3], Ah[3], Al[3]);
        uint32_t v1[4][4];
        #pragma unroll
        for (int nf2 = 0; nf2 < 4; nf2++) {
            int row = kb2 * 16 + g1 * 8 + j;
            int c = nh * 8 + nf2 * 2 + g2;
            ldsm4t(v1[nf2], sb + AV1 + row * 256 + (((uint32_t)c ^ (row & 7)) << 4));
        }
        #pragma unroll
        for (int nf = 0; nf < 8; nf++) {
            const uint32_t* bb = &v1[nf >> 1][(nf & 1) * 2];
            mma_f16(o[nf], Ah, bb);
            mma_f16(o[nf], Al, bb);
        }
    }
    // ---- inter: o += q @ S ----
    #pragma unroll
    for (int kb = 0; kb < 8; kb++) {
        uint32_t q1[4];
        {
            int row = mrow + arow;
            int c = kb * 2 + asel;
            ldsm4(q1, sb + AQ1 + row * 256 + (((uint32_t)c ^ (row & 7)) << 4));
        }
        uint32_t s1[4][4];
        #pragma unroll
        for (int nf2 = 0; nf2 < 4; nf2++) {
            int row = kb * 16 + g1 * 8 + j;
            int c = nh * 8 + nf2 * 2 + g2;
            ldsm4t(s1[nf2], sb + AS1 + row * 256 + (((uint32_t)c ^ (row & 7)) << 4));
        }
        #pragma unroll
        for (int nf = 0; nf < 8; nf++) {
            const uint32_t* bb = &s1[nf >> 1][(nf & 1) * 2];
            mma_f16(o[nf], q1, bb);
        }
    }
    // ---- epilogue: write o as single fp16 plane ----
    #pragma unroll
    for (int nf = 0; nf < 8; nf++) {
        int col = h * HD + nh * 64 + nf * 8 + c0;
        size_t pA = (grow + mrow + r0) * (DD / 2) + (col >> 1);
        size_t pB = (grow + mrow + r0 + 8) * (DD / 2) + (col >> 1);
        O1[pA] = pk2h(o[nf][0], o[nf][1]);
        O1[pB] = pk2h(o[nf][2], o[nf][3]);
    }
}

// ---------------------------------------------------------------------------
extern "C" void kernel_launch(void* const* d_in, const int* in_sizes, int n_in,
                              void* d_out, int out_size) {
    const float* x  = (const float*)d_in[0];
    const float* Wq = (const float*)d_in[1];
    const float* Wk = (const float*)d_in[2];
    const float* Wv = (const float*)d_in[3];
    const float* Wo = (const float*)d_in[4];
    float* out = (float*)d_out;

    __half *px1, *pw1, *pq1, *pk1, *pv1, *po1, *pS1, *pKV;
    cudaGetSymbolAddress((void**)&px1, g_x1);
    cudaGetSymbolAddress((void**)&pw1, g_w1);
    cudaGetSymbolAddress((void**)&pq1, g_q1);
    cudaGetSymbolAddress((void**)&pk1, g_k1);
    cudaGetSymbolAddress((void**)&pv1, g_v1);
    cudaGetSymbolAddress((void**)&po1, g_o1);
    cudaGetSymbolAddress((void**)&pS1, g_S1);
    cudaGetSymbolAddress((void**)&pKV, g_KV);

    cudaFuncSetAttribute(gemm_mma, cudaFuncAttributeMaxDynamicSharedMemorySize, GEMM_SMEM);
    cudaFuncSetAttribute(kv_mma,   cudaFuncAttributeMaxDynamicSharedMemorySize, KV_SMEM);
    cudaFuncSetAttribute(attn_mma, cudaFuncAttributeMaxDynamicSharedMemorySize, ATTN_SMEM);

    // converts: x and all W -> single fp16 planes
    cvt1<<<(MROWS * DD) / 1024, 256>>>(x, px1);
    dim3 wgrid(WSZ / 1024, 4);
    cvt_w4<<<wgrid, 256>>>(Wq, Wk, Wv, Wo, pw1);

    // fused Q,K,V projections (B = [Wq; Wk; Wv] contiguous in g_w1)
    dim3 qkvgrid(3 * DD / 128, MROWS / 128);   // (48, 64)
    gemm_mma<<<qkvgrid, 256, GEMM_SMEM>>>(px1, pw1, nullptr,
                                          (uint32_t*)pq1, (uint32_t*)pk1,
                                          (uint32_t*)pv1);

    kv_mma<<<NBH * NC, 256, KV_SMEM>>>(pk1, pv1, (uint32_t*)pKV);
    scan_kernel<<<(NBH * 8192) / 256, 256>>>((const uint32_t*)pKV, (uint32_t*)pS1);
    attn_mma<<<NBH * NC, 256, ATTN_SMEM>>>(pq1, pk1, pv1, pS1, (uint32_t*)po1);

    // output projection (fp32 out)
    dim3 ogrid(DD / 128, MROWS / 128);         // (16, 64)
    gemm_mma<<<ogrid, 256, GEMM_SMEM>>>(po1, pw1 + 3 * (size_t)WSZ, out,
                                        nullptr, nullptr, nullptr);

    (void)in_sizes; (void)n_in; (void)out_size;
}